// round 4
// baseline (speedup 1.0000x reference)
#include <cuda_runtime.h>
#include <cstddef>

// ---------------- problem dims ----------------
#define TT 24          // seq len
#define DD 300         // glove dim
#define HH 256         // GRU hidden / z dim
#define NTV 6000       // tweet nodes
#define NUV 4000       // user nodes
#define NN 10000       // total nodes
#define FF 512         // user feat size
#define ZZ 256         // z dim
#define EE 80000       // edges
#define BB 2000        // batch (source tweets)
#define CC1 64         // GAT1 out channels
#define CC2 100        // GAT2 out channels
#define NHEADS 8
#define GG 768         // 3*H
#define MM0 (TT*NTV)   // 144000
#define ETOT (EE+NN)   // 90000 (edges + self loops)

// ---------------- scratch (device globals; no allocation allowed) ----------------
__device__ float g_GI0[(size_t)MM0*GG];
__device__ float g_GI1[(size_t)MM0*GG];
__device__ float g_OUT0[(size_t)MM0*HH];
__device__ float g_GH[NTV*GG];
__device__ float g_h0[NTV*HH];
__device__ float g_h1[NTV*HH];
__device__ int   g_tok[MM0];
__device__ float g_mu[NUV*ZZ];
__device__ float g_lv[NUV*ZZ];
__device__ float g_zbuf[NUV*ZZ];
__device__ float g_rec[NUV*FF];
__device__ float g_xin[NN*HH];
__device__ float g_xp1[NN*NHEADS*CC1];
__device__ float g_as1[NN*NHEADS];
__device__ float g_ad1[NN*NHEADS];
__device__ float g_e1[ETOT*NHEADS];
__device__ float g_emax1[NN*NHEADS];
__device__ float g_den1[NN*NHEADS];
__device__ float g_agg1[NN*NHEADS*CC1];
__device__ float g_xp2[NN*CC2];
__device__ float g_as2[NN];
__device__ float g_ad2[NN];
__device__ float g_e2[ETOT];
__device__ float g_emax2[NN];
__device__ float g_den2[NN];
__device__ float g_acc[2];

// ---------------- small helpers ----------------
__device__ __forceinline__ float sigmoidf_(float x) { return 1.f / (1.f + expf(-x)); }

__device__ __forceinline__ void atomicMaxFloat(float* addr, float val) {
    int old = __float_as_int(*addr);
    while (__int_as_float(old) < val) {
        int assumed = old;
        old = atomicCAS((int*)addr, assumed, __float_as_int(val));
        if (old == assumed) break;
    }
}

__device__ __forceinline__ void block_reduce_add(float v, float* target) {
    #pragma unroll
    for (int o = 16; o > 0; o >>= 1) v += __shfl_down_sync(0xffffffffu, v, o);
    __shared__ float s[8];
    int lane = threadIdx.x & 31, w = threadIdx.x >> 5;
    if (lane == 0) s[w] = v;
    __syncthreads();
    if (w == 0) {
        v = (lane < (int)(blockDim.x >> 5)) ? s[lane] : 0.f;
        #pragma unroll
        for (int o = 4; o > 0; o >>= 1) v += __shfl_down_sync(0xffffffffu, v, o);
        if (lane == 0) atomicAdd(target, v);
    }
}

// ---------------- generic fp32 GEMM: C = A @ op(B) (+bias) ----------------
// BT=true : B is (N,K) row-major, C[m][n] = sum_k A[m][k]*B[n][k]   (x @ W^T)
// BT=false: B is (K,N) row-major, C[m][n] = sum_k A[m][k]*B[k][n]   (x @ W)
// GATHER  : A row m is A[rowidx[m]] (embedding gather fused into the GEMM)
template<bool BT, bool GATHER>
__global__ __launch_bounds__(256)
void gemm_k(const float* __restrict__ A, const float* __restrict__ Bm,
            const float* __restrict__ bias, float* __restrict__ Cc,
            int M, int Nc, int K, const int* __restrict__ rowidx)
{
    __shared__ float As[8][128];
    __shared__ float Bs[8][128];
    const int tid = threadIdx.x;
    const int bm = blockIdx.y * 128;
    const int bn = blockIdx.x * 128;
    const int tr = (tid >> 4) << 3;  // 0..120
    const int tc = (tid & 15) << 3;  // 0..120
    float acc[8][8];
    #pragma unroll
    for (int i = 0; i < 8; i++)
        #pragma unroll
        for (int j = 0; j < 8; j++) acc[i][j] = 0.f;

    const int arow = tid >> 1;        // 0..127
    const int acol = (tid & 1) << 2;  // 0 or 4
    const bool arow_ok = (bm + arow) < M;
    long abase = 0;
    if (arow_ok) {
        long r = GATHER ? (long)rowidx[bm + arow] : (long)(bm + arow);
        abase = r * (long)K;
    }
    long bbase = 0;
    bool brow_ok = true;
    if (BT) {
        brow_ok = (bn + arow) < Nc;
        if (brow_ok) bbase = (long)(bn + arow) * (long)K;
    }
    const int bkrow = tid >> 5;        // 0..7
    const int bncol = (tid & 31) << 2; // 0..124

    for (int kt = 0; kt < K; kt += 8) {
        #pragma unroll
        for (int i = 0; i < 4; i++) {
            int k = kt + acol + i;
            As[acol + i][arow] = (arow_ok && k < K) ? A[abase + k] : 0.f;
        }
        if (BT) {
            #pragma unroll
            for (int i = 0; i < 4; i++) {
                int k = kt + acol + i;
                Bs[acol + i][arow] = (brow_ok && k < K) ? Bm[bbase + k] : 0.f;
            }
        } else {
            int k = kt + bkrow;
            #pragma unroll
            for (int i = 0; i < 4; i++) {
                int n = bn + bncol + i;
                Bs[bkrow][bncol + i] = (k < K && n < Nc) ? Bm[(long)k * Nc + n] : 0.f;
            }
        }
        __syncthreads();
        #pragma unroll
        for (int k = 0; k < 8; k++) {
            float af[8], bf[8];
            #pragma unroll
            for (int i = 0; i < 8; i++) af[i] = As[k][tr + i];
            #pragma unroll
            for (int j = 0; j < 8; j++) bf[j] = Bs[k][tc + j];
            #pragma unroll
            for (int i = 0; i < 8; i++)
                #pragma unroll
                for (int j = 0; j < 8; j++)
                    acc[i][j] = fmaf(af[i], bf[j], acc[i][j]);
        }
        __syncthreads();
    }
    #pragma unroll
    for (int i = 0; i < 8; i++) {
        int row = bm + tr + i;
        if (row >= M) continue;
        #pragma unroll
        for (int j = 0; j < 8; j++) {
            int col = bn + tc + j;
            if (col < Nc)
                Cc[(long)row * Nc + col] = acc[i][j] + (bias ? bias[col] : 0.f);
        }
    }
}

// ---------------- elementwise / utility kernels ----------------
__global__ void fill_k(float* p, float v, int n) {
    int i = blockIdx.x * blockDim.x + threadIdx.x;
    if (i < n) p[i] = v;
}
__global__ void copy_k(float* dst, const float* src, int n) {
    int i = blockIdx.x * blockDim.x + threadIdx.x;
    if (i < n) dst[i] = src[i];
}
// tok[t*NT+n] = gnf[n*T+t]  (xe = emb[gnf].transpose(1,0,2))
__global__ void tok_k(int* tok, const int* gnf) {
    int i = blockIdx.x * blockDim.x + threadIdx.x;
    if (i >= MM0) return;
    int t = i / NTV, n = i % NTV;
    tok[i] = gnf[n * TT + t];
}
// torch GRU gate math (gate order r,z,n), in-place h update
__global__ void gru_gate_k(const float* __restrict__ GI, const float* __restrict__ GH,
                           float* __restrict__ h, float* __restrict__ o) {
    int idx = blockIdx.x * blockDim.x + threadIdx.x;
    if (idx >= NTV * HH) return;
    int n = idx >> 8, j = idx & 255;
    const float* gi = GI + (long)n * GG;
    const float* gh = GH + (long)n * GG;
    float r = sigmoidf_(gi[j] + gh[j]);
    float z = sigmoidf_(gi[HH + j] + gh[HH + j]);
    float nn = tanhf(gi[2 * HH + j] + r * gh[2 * HH + j]);
    float hv = h[idx];
    float hn = (1.f - z) * nn + z * hv;
    h[idx] = hn;
    if (o) o[idx] = hn;
}
// z = mu + exp(0.5*lv)*eps ; accumulate KL sum
__global__ void vae_z_kl_k(const float* mu, const float* lv, const float* eps,
                           float* z, float* acc) {
    int i = blockIdx.x * blockDim.x + threadIdx.x;
    float term = 0.f;
    if (i < NUV * ZZ) {
        float m = mu[i], l = lv[i];
        z[i] = m + expf(0.5f * l) * eps[i];
        term = 1.f + l - m * m - expf(l);
    }
    block_reduce_add(term, &acc[0]);
}
__global__ void rec_loss_k(const float* rec, const float* uf, float* acc) {
    int i = blockIdx.x * blockDim.x + threadIdx.x;
    float term = 0.f;
    if (i < NUV * FF) {
        float d = rec[i] - uf[i];
        term = d * d;
    }
    block_reduce_add(term, &acc[1]);
}
// x_in = concat(hn[:B], z, hn[B:])
__global__ void assemble_k(const float* hn, const float* z, float* xin) {
    int i = blockIdx.x * blockDim.x + threadIdx.x;
    if (i >= NN * HH) return;
    int row = i >> 8, j = i & 255;
    float v;
    if (row < BB)            v = hn[row * HH + j];
    else if (row < BB + NUV) v = z[(row - BB) * ZZ + j];
    else                     v = hn[(row - NUV) * HH + j];
    xin[i] = v;
}
// per-node attention dot products
__global__ void asad_k(const float* __restrict__ xp, const float* __restrict__ a_src,
                       const float* __restrict__ a_dst, float* as_n, float* ad_n,
                       int heads, int C) {
    int idx = blockIdx.x * blockDim.x + threadIdx.x;
    if (idx >= NN * heads) return;
    int node = idx / heads, h = idx % heads;
    const float* row = xp + (long)node * heads * C + h * C;
    float s = 0.f, d = 0.f;
    for (int c = 0; c < C; c++) { float v = row[c]; s += v * a_src[h * C + c]; d += v * a_dst[h * C + c]; }
    as_n[idx] = s; ad_n[idx] = d;
}
__device__ __forceinline__ void edge_sd(int e, const int* ei, int& s, int& d) {
    if (e < EE) { s = ei[e]; d = ei[EE + e]; } else { s = d = e - EE; }
}
// pass A: logits + segment max over dst
__global__ void edgeA_k(const float* as_n, const float* ad_n, const int* ei,
                        float* ebuf, float* emax, int heads) {
    int idx = blockIdx.x * blockDim.x + threadIdx.x;
    if (idx >= ETOT * heads) return;
    int e = idx / heads, h = idx % heads;
    int s, d; edge_sd(e, ei, s, d);
    float v = as_n[s * heads + h] + ad_n[d * heads + h];
    v = v > 0.f ? v : 0.2f * v;  // leaky_relu(0.2)
    ebuf[idx] = v;
    atomicMaxFloat(&emax[d * heads + h], v);
}
// pass B: exp + segment sum
__global__ void edgeB_k(const int* ei, float* ebuf, const float* emax,
                        float* den, int heads) {
    int idx = blockIdx.x * blockDim.x + threadIdx.x;
    if (idx >= ETOT * heads) return;
    int e = idx / heads, h = idx % heads;
    int s, d; edge_sd(e, ei, s, d);
    float ee = expf(ebuf[idx] - emax[d * heads + h]);
    ebuf[idx] = ee;
    atomicAdd(&den[d * heads + h], ee);
}
// pass C: weighted scatter (float4 loads, 4 scalar atomics)
__global__ void edgeC_k(const float* __restrict__ xp, const float* __restrict__ ebuf,
                        const float* __restrict__ den, const int* __restrict__ ei,
                        float* __restrict__ agg, int heads, int C) {
    int Q = heads * C / 4;
    long idx = (long)blockIdx.x * blockDim.x + threadIdx.x;
    if (idx >= (long)ETOT * Q) return;
    int e = (int)(idx / Q), q = (int)(idx % Q);
    int c0 = q * 4, h = c0 / C;
    int s, d; edge_sd(e, ei, s, d);
    float al = ebuf[e * heads + h] / den[d * heads + h];
    const float4 v = *(const float4*)(xp + (long)s * heads * C + c0);
    float* dst = agg + (long)d * heads * C + c0;
    atomicAdd(dst + 0, v.x * al);
    atomicAdd(dst + 1, v.y * al);
    atomicAdd(dst + 2, v.z * al);
    atomicAdd(dst + 3, v.w * al);
}
__global__ void addbias_k(float* x, const float* b, int cols, int total) {
    int i = blockIdx.x * blockDim.x + threadIdx.x;
    if (i < total) x[i] += b[i % cols];
}
__global__ void scalars_k(const float* acc, float* out, int os) {
    if (threadIdx.x == 0) {
        out[os - 2] = -0.5f * acc[0] / (float)NUV;           // kl_loss
        out[os - 1] = acc[1] / ((float)NUV * (float)FF);     // rec_loss
    }
}

// ---------------- host orchestration ----------------
static inline int cd(long a, long b) { return (int)((a + b - 1) / b); }

extern "C" void kernel_launch(void* const* d_in, const int* in_sizes, int n_in,
                              void* d_out, int out_size) {
    (void)in_sizes; (void)n_in;
    const float* user_feats = (const float*)d_in[1];
    const int*   gnf  = (const int*)d_in[2];
    const int*   ei   = (const int*)d_in[3];
    const float* emb  = (const float*)d_in[4];
    const float* w_ih0 = (const float*)d_in[5],  *w_hh0 = (const float*)d_in[6];
    const float* b_ih0 = (const float*)d_in[7],  *b_hh0 = (const float*)d_in[8];
    const float* w_ih1 = (const float*)d_in[9],  *w_hh1 = (const float*)d_in[10];
    const float* b_ih1 = (const float*)d_in[11], *b_hh1 = (const float*)d_in[12];
    const float* h0    = (const float*)d_in[13];
    const float* w_mu  = (const float*)d_in[14], *b_mu  = (const float*)d_in[15];
    const float* w_lv  = (const float*)d_in[16], *b_lv  = (const float*)d_in[17];
    const float* w_dec = (const float*)d_in[18], *b_dec = (const float*)d_in[19];
    const float* veps  = (const float*)d_in[20];
    const float* w1 = (const float*)d_in[21], *a_src1 = (const float*)d_in[22];
    const float* a_dst1 = (const float*)d_in[23], *b1 = (const float*)d_in[24];
    const float* w2 = (const float*)d_in[25], *a_src2 = (const float*)d_in[26];
    const float* a_dst2 = (const float*)d_in[27], *b2 = (const float*)d_in[28];
    float* out = (float*)d_out;

    float *GI0, *GI1, *OUT0, *GH, *h0b, *h1b, *mu, *lv, *z, *rec, *xin;
    float *xp1, *as1, *ad1, *e1, *emax1, *den1, *agg1;
    float *xp2, *as2, *ad2, *e2, *emax2, *den2, *acc;
    int* tok;
    cudaGetSymbolAddress((void**)&GI0, g_GI0);
    cudaGetSymbolAddress((void**)&GI1, g_GI1);
    cudaGetSymbolAddress((void**)&OUT0, g_OUT0);
    cudaGetSymbolAddress((void**)&GH, g_GH);
    cudaGetSymbolAddress((void**)&h0b, g_h0);
    cudaGetSymbolAddress((void**)&h1b, g_h1);
    cudaGetSymbolAddress((void**)&tok, g_tok);
    cudaGetSymbolAddress((void**)&mu, g_mu);
    cudaGetSymbolAddress((void**)&lv, g_lv);
    cudaGetSymbolAddress((void**)&z, g_zbuf);
    cudaGetSymbolAddress((void**)&rec, g_rec);
    cudaGetSymbolAddress((void**)&xin, g_xin);
    cudaGetSymbolAddress((void**)&xp1, g_xp1);
    cudaGetSymbolAddress((void**)&as1, g_as1);
    cudaGetSymbolAddress((void**)&ad1, g_ad1);
    cudaGetSymbolAddress((void**)&e1, g_e1);
    cudaGetSymbolAddress((void**)&emax1, g_emax1);
    cudaGetSymbolAddress((void**)&den1, g_den1);
    cudaGetSymbolAddress((void**)&agg1, g_agg1);
    cudaGetSymbolAddress((void**)&xp2, g_xp2);
    cudaGetSymbolAddress((void**)&as2, g_as2);
    cudaGetSymbolAddress((void**)&ad2, g_ad2);
    cudaGetSymbolAddress((void**)&e2, g_e2);
    cudaGetSymbolAddress((void**)&emax2, g_emax2);
    cudaGetSymbolAddress((void**)&den2, g_den2);
    cudaGetSymbolAddress((void**)&acc, g_acc);

    const dim3 blk(256);

    // ---- per-launch init (determinism) ----
    fill_k<<<1, 256>>>(acc, 0.f, 2);
    fill_k<<<cd(NN * NHEADS, 256), 256>>>(emax1, -1e30f, NN * NHEADS);
    fill_k<<<cd(NN * NHEADS, 256), 256>>>(den1, 0.f, NN * NHEADS);
    fill_k<<<cd(NN * NHEADS * CC1, 256), 256>>>(agg1, 0.f, NN * NHEADS * CC1);
    fill_k<<<cd(NN, 256), 256>>>(emax2, -1e30f, NN);
    fill_k<<<cd(NN, 256), 256>>>(den2, 0.f, NN);
    fill_k<<<cd(NN * CC2, 256), 256>>>(out, 0.f, NN * CC2);  // GAT2 agg target
    copy_k<<<cd(NTV * HH, 256), 256>>>(h0b, h0, NTV * HH);
    copy_k<<<cd(NTV * HH, 256), 256>>>(h1b, h0 + NTV * HH, NTV * HH);
    tok_k<<<cd(MM0, 256), 256>>>(tok, gnf);

    // ---- GRU layer 0: batched input projection (gather fused) ----
    {
        dim3 g(cd(GG, 128), cd(MM0, 128));
        gemm_k<true, true><<<g, blk>>>(emb, w_ih0, b_ih0, GI0, MM0, GG, DD, tok);
    }
    for (int t = 0; t < TT; t++) {
        dim3 g(cd(GG, 128), cd(NTV, 128));
        gemm_k<true, false><<<g, blk>>>(h0b, w_hh0, b_hh0, GH, NTV, GG, HH, nullptr);
        gru_gate_k<<<cd(NTV * HH, 256), 256>>>(GI0 + (size_t)t * NTV * GG, GH, h0b,
                                               OUT0 + (size_t)t * NTV * HH);
    }
    // ---- GRU layer 1: batched input projection from OUT0 ----
    {
        dim3 g(cd(GG, 128), cd(MM0, 128));
        gemm_k<true, false><<<g, blk>>>(OUT0, w_ih1, b_ih1, GI1, MM0, GG, HH, nullptr);
    }
    for (int t = 0; t < TT; t++) {
        dim3 g(cd(GG, 128), cd(NTV, 128));
        gemm_k<true, false><<<g, blk>>>(h1b, w_hh1, b_hh1, GH, NTV, GG, HH, nullptr);
        gru_gate_k<<<cd(NTV * HH, 256), 256>>>(GI1 + (size_t)t * NTV * GG, GH, h1b, nullptr);
    }

    // ---- VAE ----
    {
        dim3 g(cd(ZZ, 128), cd(NUV, 128));
        gemm_k<true, false><<<g, blk>>>(user_feats, w_mu, b_mu, mu, NUV, ZZ, FF, nullptr);
        gemm_k<true, false><<<g, blk>>>(user_feats, w_lv, b_lv, lv, NUV, ZZ, FF, nullptr);
    }
    vae_z_kl_k<<<cd(NUV * ZZ, 256), 256>>>(mu, lv, veps, z, acc);
    {
        dim3 g(cd(FF, 128), cd(NUV, 128));
        gemm_k<true, false><<<g, blk>>>(z, w_dec, b_dec, rec, NUV, FF, ZZ, nullptr);
    }
    rec_loss_k<<<cd(NUV * FF, 256), 256>>>(rec, user_feats, acc);

    // ---- node feature assembly ----
    assemble_k<<<cd(NN * HH, 256), 256>>>(h1b, z, xin);

    // ---- GAT layer 1 (8 heads x 64, concat) ----
    {
        dim3 g(cd(NHEADS * CC1, 128), cd(NN, 128));
        gemm_k<false, false><<<g, blk>>>(xin, w1, nullptr, xp1, NN, NHEADS * CC1, HH, nullptr);
    }
    asad_k<<<cd(NN * NHEADS, 256), 256>>>(xp1, a_src1, a_dst1, as1, ad1, NHEADS, CC1);
    edgeA_k<<<cd((long)ETOT * NHEADS, 256), 256>>>(as1, ad1, ei, e1, emax1, NHEADS);
    edgeB_k<<<cd((long)ETOT * NHEADS, 256), 256>>>(ei, e1, emax1, den1, NHEADS);
    edgeC_k<<<cd((long)ETOT * NHEADS * CC1 / 4, 256), 256>>>(xp1, e1, den1, ei, agg1, NHEADS, CC1);
    addbias_k<<<cd(NN * NHEADS * CC1, 256), 256>>>(agg1, b1, NHEADS * CC1, NN * NHEADS * CC1);

    // ---- GAT layer 2 (1 head x 100, mean == identity) ----
    {
        dim3 g(cd(CC2, 128), cd(NN, 128));
        gemm_k<false, false><<<g, blk>>>(agg1, w2, nullptr, xp2, NN, CC2, NHEADS * CC1, nullptr);
    }
    asad_k<<<cd(NN, 256), 256>>>(xp2, a_src2, a_dst2, as2, ad2, 1, CC2);
    edgeA_k<<<cd(ETOT, 256), 256>>>(as2, ad2, ei, e2, emax2, 1);
    edgeB_k<<<cd(ETOT, 256), 256>>>(ei, e2, emax2, den2, 1);
    edgeC_k<<<cd((long)ETOT * CC2 / 4, 256), 256>>>(xp2, e2, den2, ei, out, 1, CC2);
    addbias_k<<<cd(NN * CC2, 256), 256>>>(out, b2, CC2, NN * CC2);

    // ---- scalar losses ----
    scalars_k<<<1, 32>>>(acc, out, out_size);
}

// round 6
// speedup vs baseline: 1.0042x; 1.0042x over previous
#include <cuda_runtime.h>
#include <cstddef>

// ---------------- problem dims ----------------
#define TT 24          // seq len
#define DD 300         // glove dim
#define HH 256         // GRU hidden / z dim
#define NTV 6000       // tweet nodes
#define NUV 4000       // user nodes
#define NN 10000       // total nodes
#define FF 512         // user feat size
#define ZZ 256         // z dim
#define EE 80000       // edges
#define BB 2000        // batch (source tweets)
#define CC1 64         // GAT1 out channels
#define CC2 100        // GAT2 out channels
#define NHEADS 8
#define GG 768         // 3*H
#define MM0 (TT*NTV)   // 144000
#define ETOT (EE+NN)   // 90000 (edges + self loops)

// ---------------- scratch (device globals; no allocation allowed) ----------------
__device__ float g_GI0[(size_t)MM0*GG];
__device__ float g_GI1[(size_t)MM0*GG];
__device__ float g_OUT0[(size_t)MM0*HH];
__device__ float g_GH[NTV*GG];
__device__ float g_h0[NTV*HH];
__device__ float g_h1[NTV*HH];
__device__ int   g_tok[MM0];
__device__ float g_mu[NUV*ZZ];
__device__ float g_lv[NUV*ZZ];
__device__ float g_zbuf[NUV*ZZ];
__device__ float g_rec[NUV*FF];
__device__ float g_xin[NN*HH];
__device__ float g_xp1[NN*NHEADS*CC1];
__device__ float g_as1[NN*NHEADS];
__device__ float g_ad1[NN*NHEADS];
__device__ float g_e1[ETOT*NHEADS];
__device__ float g_emax1[NN*NHEADS];
__device__ float g_den1[NN*NHEADS];
__device__ float g_agg1[NN*NHEADS*CC1];
__device__ float g_xp2[NN*CC2];
__device__ float g_as2[NN];
__device__ float g_ad2[NN];
__device__ float g_e2[ETOT];
__device__ float g_emax2[NN];
__device__ float g_den2[NN];
__device__ float g_acc[2];

// ---------------- small helpers ----------------
__device__ __forceinline__ float sigmoidf_(float x) { return 1.f / (1.f + expf(-x)); }

__device__ __forceinline__ void atomicMaxFloat(float* addr, float val) {
    int old = __float_as_int(*addr);
    while (__int_as_float(old) < val) {
        int assumed = old;
        old = atomicCAS((int*)addr, assumed, __float_as_int(val));
        if (old == assumed) break;
    }
}

__device__ __forceinline__ void redAdd4(float* addr, float a, float b, float c, float d) {
    asm volatile("red.global.add.v4.f32 [%0], {%1, %2, %3, %4};"
                 :: "l"(addr), "f"(a), "f"(b), "f"(c), "f"(d) : "memory");
}

__device__ __forceinline__ void block_reduce_add(float v, float* target) {
    #pragma unroll
    for (int o = 16; o > 0; o >>= 1) v += __shfl_down_sync(0xffffffffu, v, o);
    __shared__ float s[8];
    int lane = threadIdx.x & 31, w = threadIdx.x >> 5;
    if (lane == 0) s[w] = v;
    __syncthreads();
    if (w == 0) {
        v = (lane < (int)(blockDim.x >> 5)) ? s[lane] : 0.f;
        #pragma unroll
        for (int o = 4; o > 0; o >>= 1) v += __shfl_down_sync(0xffffffffu, v, o);
        if (lane == 0) atomicAdd(target, v);
    }
}

// ---------------- generic fp32 GEMM (FFMA2 inner loop): C = A @ op(B) (+bias) ----------------
// BT=true : B is (N,K) row-major, C[m][n] = sum_k A[m][k]*B[n][k]   (x @ W^T)
// BT=false: B is (K,N) row-major, C[m][n] = sum_k A[m][k]*B[k][n]   (x @ W)
// GATHER  : A row m is A[rowidx[m]] (embedding gather fused into the GEMM)
template<bool BT, bool GATHER>
__global__ __launch_bounds__(256)
void gemm_k(const float* __restrict__ A, const float* __restrict__ Bm,
            const float* __restrict__ bias, float* __restrict__ Cc,
            int M, int Nc, int K, const int* __restrict__ rowidx)
{
    __shared__ float As[8][128];
    __shared__ float Bs[8][128];
    const int tid = threadIdx.x;
    const int bm = blockIdx.y * 128;
    const int bn = blockIdx.x * 128;
    const int tr = (tid >> 4) << 3;  // 0..120
    const int tc = (tid & 15) << 3;  // 0..120

    // packed f32x2 accumulators: acc2[i][j] holds columns (2j, 2j+1) of row i
    unsigned long long acc2[8][4];
    #pragma unroll
    for (int i = 0; i < 8; i++)
        #pragma unroll
        for (int j = 0; j < 4; j++) acc2[i][j] = 0ull;

    const int arow = tid >> 1;        // 0..127
    const int acol = (tid & 1) << 2;  // 0 or 4
    const bool arow_ok = (bm + arow) < M;
    long abase = 0;
    if (arow_ok) {
        long r = GATHER ? (long)rowidx[bm + arow] : (long)(bm + arow);
        abase = r * (long)K;
    }
    long bbase = 0;
    bool brow_ok = true;
    if (BT) {
        brow_ok = (bn + arow) < Nc;
        if (brow_ok) bbase = (long)(bn + arow) * (long)K;
    }
    const int bkrow = tid >> 5;        // 0..7
    const int bncol = (tid & 31) << 2; // 0..124

    for (int kt = 0; kt < K; kt += 8) {
        #pragma unroll
        for (int i = 0; i < 4; i++) {
            int k = kt + acol + i;
            As[acol + i][arow] = (arow_ok && k < K) ? A[abase + k] : 0.f;
        }
        if (BT) {
            #pragma unroll
            for (int i = 0; i < 4; i++) {
                int k = kt + acol + i;
                Bs[acol + i][arow] = (brow_ok && k < K) ? Bm[bbase + k] : 0.f;
            }
        } else {
            int k = kt + bkrow;
            #pragma unroll
            for (int i = 0; i < 4; i++) {
                int n = bn + bncol + i;
                Bs[bkrow][bncol + i] = (k < K && n < Nc) ? Bm[(long)k * Nc + n] : 0.f;
            }
        }
        __syncthreads();
        #pragma unroll
        for (int k = 0; k < 8; k++) {
            float af[8];
            *(float4*)(af)     = *(const float4*)(&As[k][tr]);
            *(float4*)(af + 4) = *(const float4*)(&As[k][tr + 4]);
            unsigned long long b2[4];
            #pragma unroll
            for (int j = 0; j < 4; j++)
                b2[j] = *(const unsigned long long*)(&Bs[k][tc + 2 * j]);
            #pragma unroll
            for (int i = 0; i < 8; i++) {
                unsigned long long a2;
                asm("mov.b64 %0, {%1, %1};" : "=l"(a2) : "r"(__float_as_uint(af[i])));
                #pragma unroll
                for (int j = 0; j < 4; j++)
                    asm("fma.rn.f32x2 %0, %1, %2, %0;"
                        : "+l"(acc2[i][j]) : "l"(a2), "l"(b2[j]));
            }
        }
        __syncthreads();
    }
    #pragma unroll
    for (int i = 0; i < 8; i++) {
        int row = bm + tr + i;
        if (row >= M) continue;
        float vals[8];
        #pragma unroll
        for (int j = 0; j < 4; j++) {
            float2 p = *(float2*)&acc2[i][j];
            vals[2 * j] = p.x; vals[2 * j + 1] = p.y;
        }
        #pragma unroll
        for (int j = 0; j < 8; j++) {
            int col = bn + tc + j;
            if (col < Nc)
                Cc[(long)row * Nc + col] = vals[j] + (bias ? bias[col] : 0.f);
        }
    }
}

// ---------------- fused init: all zero/neg-inf fills in one launch ----------------
#define INIT_E1 (NN*NHEADS)                       // emax1  <- -1e30
#define INIT_D1 (NN*NHEADS)                       // den1   <- 0
#define INIT_AG (NN*NHEADS*CC1)                   // agg1   <- 0
#define INIT_O  (NN*CC2)                          // out    <- 0
#define INIT_TOTAL (INIT_E1 + INIT_D1 + INIT_AG + NN + NN + INIT_O + 2)
__global__ void init_all_k(float* emax1, float* den1, float* agg1,
                           float* emax2, float* den2, float* out, float* acc) {
    int i = blockIdx.x * blockDim.x + threadIdx.x;
    if (i >= INIT_TOTAL) return;
    if (i < INIT_E1) { emax1[i] = -1e30f; return; }
    i -= INIT_E1;
    if (i < INIT_D1) { den1[i] = 0.f; return; }
    i -= INIT_D1;
    if (i < INIT_AG) { agg1[i] = 0.f; return; }
    i -= INIT_AG;
    if (i < NN) { emax2[i] = -1e30f; return; }
    i -= NN;
    if (i < NN) { den2[i] = 0.f; return; }
    i -= NN;
    if (i < INIT_O) { out[i] = 0.f; return; }
    i -= INIT_O;
    acc[i] = 0.f;
}

// ---------------- elementwise / utility kernels ----------------
__global__ void copy_k(float* dst, const float* src, int n) {
    int i = blockIdx.x * blockDim.x + threadIdx.x;
    if (i < n) dst[i] = src[i];
}
// tok[t*NT+n] = gnf[n*T+t]  (xe = emb[gnf].transpose(1,0,2))
__global__ void tok_k(int* tok, const int* gnf) {
    int i = blockIdx.x * blockDim.x + threadIdx.x;
    if (i >= MM0) return;
    int t = i / NTV, n = i % NTV;
    tok[i] = gnf[n * TT + t];
}
// torch GRU gate math (gate order r,z,n), in-place h update
__global__ void gru_gate_k(const float* __restrict__ GI, const float* __restrict__ GH,
                           float* __restrict__ h, float* __restrict__ o) {
    int idx = blockIdx.x * blockDim.x + threadIdx.x;
    if (idx >= NTV * HH) return;
    int n = idx >> 8, j = idx & 255;
    const float* gi = GI + (long)n * GG;
    const float* gh = GH + (long)n * GG;
    float r = sigmoidf_(gi[j] + gh[j]);
    float z = sigmoidf_(gi[HH + j] + gh[HH + j]);
    float nn = tanhf(gi[2 * HH + j] + r * gh[2 * HH + j]);
    float hv = h[idx];
    float hn = (1.f - z) * nn + z * hv;
    h[idx] = hn;
    if (o) o[idx] = hn;
}
// z = mu + exp(0.5*lv)*eps ; accumulate KL sum
__global__ void vae_z_kl_k(const float* mu, const float* lv, const float* eps,
                           float* z, float* acc) {
    int i = blockIdx.x * blockDim.x + threadIdx.x;
    float term = 0.f;
    if (i < NUV * ZZ) {
        float m = mu[i], l = lv[i];
        z[i] = m + expf(0.5f * l) * eps[i];
        term = 1.f + l - m * m - expf(l);
    }
    block_reduce_add(term, &acc[0]);
}
__global__ void rec_loss_k(const float* rec, const float* uf, float* acc) {
    int i = blockIdx.x * blockDim.x + threadIdx.x;
    float term = 0.f;
    if (i < NUV * FF) {
        float d = rec[i] - uf[i];
        term = d * d;
    }
    block_reduce_add(term, &acc[1]);
}
// x_in = concat(hn[:B], z, hn[B:])
__global__ void assemble_k(const float* hn, const float* z, float* xin) {
    int i = blockIdx.x * blockDim.x + threadIdx.x;
    if (i >= NN * HH) return;
    int row = i >> 8, j = i & 255;
    float v;
    if (row < BB)            v = hn[row * HH + j];
    else if (row < BB + NUV) v = z[(row - BB) * ZZ + j];
    else                     v = hn[(row - NUV) * HH + j];
    xin[i] = v;
}
// per-node attention dot products
__global__ void asad_k(const float* __restrict__ xp, const float* __restrict__ a_src,
                       const float* __restrict__ a_dst, float* as_n, float* ad_n,
                       int heads, int C) {
    int idx = blockIdx.x * blockDim.x + threadIdx.x;
    if (idx >= NN * heads) return;
    int node = idx / heads, h = idx % heads;
    const float* row = xp + (long)node * heads * C + h * C;
    float s = 0.f, d = 0.f;
    for (int c = 0; c < C; c++) { float v = row[c]; s += v * a_src[h * C + c]; d += v * a_dst[h * C + c]; }
    as_n[idx] = s; ad_n[idx] = d;
}
__device__ __forceinline__ void edge_sd(int e, const int* ei, int& s, int& d) {
    if (e < EE) { s = ei[e]; d = ei[EE + e]; } else { s = d = e - EE; }
}
// pass A: logits + segment max over dst
__global__ void edgeA_k(const float* as_n, const float* ad_n, const int* ei,
                        float* ebuf, float* emax, int heads) {
    int idx = blockIdx.x * blockDim.x + threadIdx.x;
    if (idx >= ETOT * heads) return;
    int e = idx / heads, h = idx % heads;
    int s, d; edge_sd(e, ei, s, d);
    float v = as_n[s * heads + h] + ad_n[d * heads + h];
    v = v > 0.f ? v : 0.2f * v;  // leaky_relu(0.2)
    ebuf[idx] = v;
    atomicMaxFloat(&emax[d * heads + h], v);
}
// pass B: exp + segment sum
__global__ void edgeB_k(const int* ei, float* ebuf, const float* emax,
                        float* den, int heads) {
    int idx = blockIdx.x * blockDim.x + threadIdx.x;
    if (idx >= ETOT * heads) return;
    int e = idx / heads, h = idx % heads;
    int s, d; edge_sd(e, ei, s, d);
    float ee = expf(ebuf[idx] - emax[d * heads + h]);
    ebuf[idx] = ee;
    atomicAdd(&den[d * heads + h], ee);
}
// pass C: weighted scatter (float4 loads, vec4 reduction stores)
__global__ void edgeC_k(const float* __restrict__ xp, const float* __restrict__ ebuf,
                        const float* __restrict__ den, const int* __restrict__ ei,
                        float* __restrict__ agg, int heads, int C) {
    int Q = heads * C / 4;
    long idx = (long)blockIdx.x * blockDim.x + threadIdx.x;
    if (idx >= (long)ETOT * Q) return;
    int e = (int)(idx / Q), q = (int)(idx % Q);
    int c0 = q * 4, h = c0 / C;
    int s, d; edge_sd(e, ei, s, d);
    float al = ebuf[e * heads + h] / den[d * heads + h];
    const float4 v = *(const float4*)(xp + (long)s * heads * C + c0);
    float* dst = agg + (long)d * heads * C + c0;
    redAdd4(dst, v.x * al, v.y * al, v.z * al, v.w * al);
}
__global__ void addbias_k(float* x, const float* b, int cols, int total) {
    int i = blockIdx.x * blockDim.x + threadIdx.x;
    if (i < total) x[i] += b[i % cols];
}
__global__ void scalars_k(const float* acc, float* out, int os) {
    if (threadIdx.x == 0) {
        out[os - 2] = -0.5f * acc[0] / (float)NUV;           // kl_loss
        out[os - 1] = acc[1] / ((float)NUV * (float)FF);     // rec_loss
    }
}

// ---------------- host orchestration ----------------
static inline int cd(long a, long b) { return (int)((a + b - 1) / b); }

extern "C" void kernel_launch(void* const* d_in, const int* in_sizes, int n_in,
                              void* d_out, int out_size) {
    (void)in_sizes; (void)n_in;
    const float* user_feats = (const float*)d_in[1];
    const int*   gnf  = (const int*)d_in[2];
    const int*   ei   = (const int*)d_in[3];
    const float* emb  = (const float*)d_in[4];
    const float* w_ih0 = (const float*)d_in[5],  *w_hh0 = (const float*)d_in[6];
    const float* b_ih0 = (const float*)d_in[7],  *b_hh0 = (const float*)d_in[8];
    const float* w_ih1 = (const float*)d_in[9],  *w_hh1 = (const float*)d_in[10];
    const float* b_ih1 = (const float*)d_in[11], *b_hh1 = (const float*)d_in[12];
    const float* h0    = (const float*)d_in[13];
    const float* w_mu  = (const float*)d_in[14], *b_mu  = (const float*)d_in[15];
    const float* w_lv  = (const float*)d_in[16], *b_lv  = (const float*)d_in[17];
    const float* w_dec = (const float*)d_in[18], *b_dec = (const float*)d_in[19];
    const float* veps  = (const float*)d_in[20];
    const float* w1 = (const float*)d_in[21], *a_src1 = (const float*)d_in[22];
    const float* a_dst1 = (const float*)d_in[23], *b1 = (const float*)d_in[24];
    const float* w2 = (const float*)d_in[25], *a_src2 = (const float*)d_in[26];
    const float* a_dst2 = (const float*)d_in[27], *b2 = (const float*)d_in[28];
    float* out = (float*)d_out;

    float *GI0, *GI1, *OUT0, *GH, *h0b, *h1b, *mu, *lv, *z, *rec, *xin;
    float *xp1, *as1, *ad1, *e1, *emax1, *den1, *agg1;
    float *xp2, *as2, *ad2, *e2, *emax2, *den2, *acc;
    int* tok;
    cudaGetSymbolAddress((void**)&GI0, g_GI0);
    cudaGetSymbolAddress((void**)&GI1, g_GI1);
    cudaGetSymbolAddress((void**)&OUT0, g_OUT0);
    cudaGetSymbolAddress((void**)&GH, g_GH);
    cudaGetSymbolAddress((void**)&h0b, g_h0);
    cudaGetSymbolAddress((void**)&h1b, g_h1);
    cudaGetSymbolAddress((void**)&tok, g_tok);
    cudaGetSymbolAddress((void**)&mu, g_mu);
    cudaGetSymbolAddress((void**)&lv, g_lv);
    cudaGetSymbolAddress((void**)&z, g_zbuf);
    cudaGetSymbolAddress((void**)&rec, g_rec);
    cudaGetSymbolAddress((void**)&xin, g_xin);
    cudaGetSymbolAddress((void**)&xp1, g_xp1);
    cudaGetSymbolAddress((void**)&as1, g_as1);
    cudaGetSymbolAddress((void**)&ad1, g_ad1);
    cudaGetSymbolAddress((void**)&e1, g_e1);
    cudaGetSymbolAddress((void**)&emax1, g_emax1);
    cudaGetSymbolAddress((void**)&den1, g_den1);
    cudaGetSymbolAddress((void**)&agg1, g_agg1);
    cudaGetSymbolAddress((void**)&xp2, g_xp2);
    cudaGetSymbolAddress((void**)&as2, g_as2);
    cudaGetSymbolAddress((void**)&ad2, g_ad2);
    cudaGetSymbolAddress((void**)&e2, g_e2);
    cudaGetSymbolAddress((void**)&emax2, g_emax2);
    cudaGetSymbolAddress((void**)&den2, g_den2);
    cudaGetSymbolAddress((void**)&acc, g_acc);

    const dim3 blk(256);

    // ---- per-launch init (determinism) ----
    init_all_k<<<cd(INIT_TOTAL, 256), 256>>>(emax1, den1, agg1, emax2, den2, out, acc);
    copy_k<<<cd(NTV * HH, 256), 256>>>(h0b, h0, NTV * HH);
    copy_k<<<cd(NTV * HH, 256), 256>>>(h1b, h0 + NTV * HH, NTV * HH);
    tok_k<<<cd(MM0, 256), 256>>>(tok, gnf);

    // ---- GRU layer 0: batched input projection (gather fused) ----
    {
        dim3 g(cd(GG, 128), cd(MM0, 128));
        gemm_k<true, true><<<g, blk>>>(emb, w_ih0, b_ih0, GI0, MM0, GG, DD, tok);
    }
    for (int t = 0; t < TT; t++) {
        dim3 g(cd(GG, 128), cd(NTV, 128));
        gemm_k<true, false><<<g, blk>>>(h0b, w_hh0, b_hh0, GH, NTV, GG, HH, nullptr);
        gru_gate_k<<<cd(NTV * HH, 256), 256>>>(GI0 + (size_t)t * NTV * GG, GH, h0b,
                                               OUT0 + (size_t)t * NTV * HH);
    }
    // ---- GRU layer 1: batched input projection from OUT0 ----
    {
        dim3 g(cd(GG, 128), cd(MM0, 128));
        gemm_k<true, false><<<g, blk>>>(OUT0, w_ih1, b_ih1, GI1, MM0, GG, HH, nullptr);
    }
    for (int t = 0; t < TT; t++) {
        dim3 g(cd(GG, 128), cd(NTV, 128));
        gemm_k<true, false><<<g, blk>>>(h1b, w_hh1, b_hh1, GH, NTV, GG, HH, nullptr);
        gru_gate_k<<<cd(NTV * HH, 256), 256>>>(GI1 + (size_t)t * NTV * GG, GH, h1b, nullptr);
    }

    // ---- VAE ----
    {
        dim3 g(cd(ZZ, 128), cd(NUV, 128));
        gemm_k<true, false><<<g, blk>>>(user_feats, w_mu, b_mu, mu, NUV, ZZ, FF, nullptr);
        gemm_k<true, false><<<g, blk>>>(user_feats, w_lv, b_lv, lv, NUV, ZZ, FF, nullptr);
    }
    vae_z_kl_k<<<cd(NUV * ZZ, 256), 256>>>(mu, lv, veps, z, acc);
    {
        dim3 g(cd(FF, 128), cd(NUV, 128));
        gemm_k<true, false><<<g, blk>>>(z, w_dec, b_dec, rec, NUV, FF, ZZ, nullptr);
    }
    rec_loss_k<<<cd(NUV * FF, 256), 256>>>(rec, user_feats, acc);

    // ---- node feature assembly ----
    assemble_k<<<cd(NN * HH, 256), 256>>>(h1b, z, xin);

    // ---- GAT layer 1 (8 heads x 64, concat) ----
    {
        dim3 g(cd(NHEADS * CC1, 128), cd(NN, 128));
        gemm_k<false, false><<<g, blk>>>(xin, w1, nullptr, xp1, NN, NHEADS * CC1, HH, nullptr);
    }
    asad_k<<<cd(NN * NHEADS, 256), 256>>>(xp1, a_src1, a_dst1, as1, ad1, NHEADS, CC1);
    edgeA_k<<<cd((long)ETOT * NHEADS, 256), 256>>>(as1, ad1, ei, e1, emax1, NHEADS);
    edgeB_k<<<cd((long)ETOT * NHEADS, 256), 256>>>(ei, e1, emax1, den1, NHEADS);
    edgeC_k<<<cd((long)ETOT * NHEADS * CC1 / 4, 256), 256>>>(xp1, e1, den1, ei, agg1, NHEADS, CC1);
    addbias_k<<<cd(NN * NHEADS * CC1, 256), 256>>>(agg1, b1, NHEADS * CC1, NN * NHEADS * CC1);

    // ---- GAT layer 2 (1 head x 100, mean == identity) ----
    {
        dim3 g(cd(CC2, 128), cd(NN, 128));
        gemm_k<false, false><<<g, blk>>>(agg1, w2, nullptr, xp2, NN, CC2, NHEADS * CC1, nullptr);
    }
    asad_k<<<cd(NN, 256), 256>>>(xp2, a_src2, a_dst2, as2, ad2, 1, CC2);
    edgeA_k<<<cd(ETOT, 256), 256>>>(as2, ad2, ei, e2, emax2, 1);
    edgeB_k<<<cd(ETOT, 256), 256>>>(ei, e2, emax2, den2, 1);
    edgeC_k<<<cd((long)ETOT * CC2 / 4, 256), 256>>>(xp2, e2, den2, ei, out, 1, CC2);
    addbias_k<<<cd(NN * CC2, 256), 256>>>(out, b2, CC2, NN * CC2);

    // ---- scalar losses ----
    scalars_k<<<1, 32>>>(acc, out, out_size);
}

// round 7
// speedup vs baseline: 1.7559x; 1.7485x over previous
#include <cuda_runtime.h>
#include <cstddef>

// ---------------- problem dims ----------------
#define TT 24          // seq len
#define DD 300         // glove dim
#define HH 256         // GRU hidden / z dim
#define NTV 6000       // tweet nodes
#define NUV 4000       // user nodes
#define NN 10000       // total nodes
#define FF 512         // user feat size
#define ZZ 256         // z dim
#define EE 80000       // edges
#define BB 2000        // batch (source tweets)
#define CC1 64         // GAT1 out channels
#define CC2 100        // GAT2 out channels
#define NHEADS 8
#define GG 768         // 3*H
#define MM0 (TT*NTV)   // 144000
#define ETOT (EE+NN)   // 90000 (edges + self loops)

// ---------------- scratch (device globals; no allocation allowed) ----------------
__device__ float g_GI0[(size_t)MM0*GG];
__device__ float g_GI1[(size_t)MM0*GG];
__device__ float g_OUT0[(size_t)MM0*HH];
__device__ float g_GH[NTV*GG];
__device__ float g_h0[NTV*HH];
__device__ float g_h1[NTV*HH];
__device__ int   g_tok[MM0];
__device__ float g_mu[NUV*ZZ];
__device__ float g_lv[NUV*ZZ];
__device__ float g_zbuf[NUV*ZZ];
__device__ float g_rec[NUV*FF];
__device__ float g_xin[NN*HH];
__device__ float g_xp1[NN*NHEADS*CC1];
__device__ float g_as1[NN*NHEADS];
__device__ float g_ad1[NN*NHEADS];
__device__ float g_e1[ETOT*NHEADS];
__device__ float g_emax1[NN*NHEADS];
__device__ float g_den1[NN*NHEADS];
__device__ float g_agg1[NN*NHEADS*CC1];
__device__ float g_xp2[NN*CC2];
__device__ float g_as2[NN];
__device__ float g_ad2[NN];
__device__ float g_e2[ETOT];
__device__ float g_emax2[NN];
__device__ float g_den2[NN];
__device__ float g_acc[2];

// ---------------- small helpers ----------------
__device__ __forceinline__ float sigmoidf_(float x) { return 1.f / (1.f + expf(-x)); }

__device__ __forceinline__ void atomicMaxFloat(float* addr, float val) {
    int old = __float_as_int(*addr);
    while (__int_as_float(old) < val) {
        int assumed = old;
        old = atomicCAS((int*)addr, assumed, __float_as_int(val));
        if (old == assumed) break;
    }
}

__device__ __forceinline__ void redAdd4(float* addr, float a, float b, float c, float d) {
    asm volatile("red.global.add.v4.f32 [%0], {%1, %2, %3, %4};"
                 :: "l"(addr), "f"(a), "f"(b), "f"(c), "f"(d) : "memory");
}

__device__ __forceinline__ void block_reduce_add(float v, float* target) {
    #pragma unroll
    for (int o = 16; o > 0; o >>= 1) v += __shfl_down_sync(0xffffffffu, v, o);
    __shared__ float s[8];
    int lane = threadIdx.x & 31, w = threadIdx.x >> 5;
    if (lane == 0) s[w] = v;
    __syncthreads();
    if (w == 0) {
        v = (lane < (int)(blockDim.x >> 5)) ? s[lane] : 0.f;
        #pragma unroll
        for (int o = 4; o > 0; o >>= 1) v += __shfl_down_sync(0xffffffffu, v, o);
        if (lane == 0) atomicAdd(target, v);
    }
}

// ================= GEMM v3: 128x128x16 tiles, conflict-free frags, =================
// ================= double-buffered smem, FFMA2 inner loop          =================
// BT=true : B is (N,K) row-major -> C = A @ B^T
// BT=false: B is (K,N) row-major -> C = A @ B
// GATHER  : A row m is A[rowidx[m]]
#define BKK 16
#define LDSM 132   // padded smem row stride (floats)

template<bool BT, bool GATHER>
__global__ __launch_bounds__(256, 2)
void gemm_k(const float* __restrict__ A, const float* __restrict__ Bm,
            const float* __restrict__ bias, float* __restrict__ Cc,
            int M, int Nc, int K, const int* __restrict__ rowidx)
{
    __shared__ float As[2][BKK * LDSM];
    __shared__ float Bs[2][BKK * LDSM];
    __shared__ int   ridx[128];

    const int tid = threadIdx.x;
    const int bm = blockIdx.y * 128;
    const int bn = blockIdx.x * 128;

    // A row indices for this block (gather or identity), -1 = out of range
    if (tid < 128) {
        int r = bm + tid;
        ridx[tid] = (r < M) ? (GATHER ? rowidx[r] : r) : -1;
    }
    __syncthreads();

    // fragment coordinates: rows {r0..r0+3, r0+64..}, cols {c0..c0+3, c0+64..}
    const int r0 = (tid >> 4) << 2;   // 0..60
    const int c0 = (tid & 15) << 2;   // 0..60

    unsigned long long acc2[8][4];    // [row 0..7][col-pair]; pairs: c0,c0+2,c0+64,c0+66
    #pragma unroll
    for (int i = 0; i < 8; i++)
        #pragma unroll
        for (int j = 0; j < 4; j++) acc2[i][j] = 0ull;

    // ---- loader coordinates ----
    // A (and B when BT): transpose path. chunk c (0..511): row=c>>2, kc=(c&3)*4
    const int la_row0 = tid >> 2,        la_kc0 = (tid & 3) << 2;
    const int la_row1 = (tid + 256) >> 2, la_kc1 = ((tid + 256) & 3) << 2;
    // B direct path. chunk c: k=c>>5, n4=(c&31)*4
    const int lb_k0 = tid >> 5,          lb_n0 = (tid & 31) << 2;
    const int lb_k1 = (tid + 256) >> 5,  lb_n1 = ((tid + 256) & 31) << 2;

    const int nTiles = (K + BKK - 1) / BKK;

    float4 pa0, pa1, pb0, pb1;

    // prefetch into registers for tile t
    auto fetch = [&](int kt, float4& a0, float4& a1, float4& b0, float4& b1) {
        const float4 zero = make_float4(0.f, 0.f, 0.f, 0.f);
        // A: row la_rowX (via ridx), cols kt+la_kcX.. (K%4==0 for all call sites)
        {
            int gr = ridx[la_row0];
            a0 = (gr >= 0 && kt + la_kc0 < K) ? *(const float4*)(A + (long)gr * K + kt + la_kc0) : zero;
            gr = ridx[la_row1];
            a1 = (gr >= 0 && kt + la_kc1 < K) ? *(const float4*)(A + (long)gr * K + kt + la_kc1) : zero;
        }
        if (BT) {
            int n = bn + la_row0;
            b0 = (n < Nc && kt + la_kc0 < K) ? *(const float4*)(Bm + (long)n * K + kt + la_kc0) : zero;
            n = bn + la_row1;
            b1 = (n < Nc && kt + la_kc1 < K) ? *(const float4*)(Bm + (long)n * K + kt + la_kc1) : zero;
        } else {
            int n = bn + lb_n0;
            b0 = (n < Nc && kt + lb_k0 < K) ? *(const float4*)(Bm + (long)(kt + lb_k0) * Nc + n) : zero;
            n = bn + lb_n1;
            b1 = (n < Nc && kt + lb_k1 < K) ? *(const float4*)(Bm + (long)(kt + lb_k1) * Nc + n) : zero;
        }
    };
    // store register-staged tile into smem buffer
    auto store = [&](int buf, const float4& a0, const float4& a1,
                     const float4& b0, const float4& b1) {
        float* as = As[buf];
        float* bs = Bs[buf];
        as[(la_kc0 + 0) * LDSM + la_row0] = a0.x;
        as[(la_kc0 + 1) * LDSM + la_row0] = a0.y;
        as[(la_kc0 + 2) * LDSM + la_row0] = a0.z;
        as[(la_kc0 + 3) * LDSM + la_row0] = a0.w;
        as[(la_kc1 + 0) * LDSM + la_row1] = a1.x;
        as[(la_kc1 + 1) * LDSM + la_row1] = a1.y;
        as[(la_kc1 + 2) * LDSM + la_row1] = a1.z;
        as[(la_kc1 + 3) * LDSM + la_row1] = a1.w;
        if (BT) {
            bs[(la_kc0 + 0) * LDSM + la_row0] = b0.x;
            bs[(la_kc0 + 1) * LDSM + la_row0] = b0.y;
            bs[(la_kc0 + 2) * LDSM + la_row0] = b0.z;
            bs[(la_kc0 + 3) * LDSM + la_row0] = b0.w;
            bs[(la_kc1 + 0) * LDSM + la_row1] = b1.x;
            bs[(la_kc1 + 1) * LDSM + la_row1] = b1.y;
            bs[(la_kc1 + 2) * LDSM + la_row1] = b1.z;
            bs[(la_kc1 + 3) * LDSM + la_row1] = b1.w;
        } else {
            *(float4*)(bs + lb_k0 * LDSM + lb_n0) = b0;
            *(float4*)(bs + lb_k1 * LDSM + lb_n1) = b1;
        }
    };

    fetch(0, pa0, pa1, pb0, pb1);
    store(0, pa0, pa1, pb0, pb1);
    __syncthreads();

    for (int t = 0; t < nTiles; t++) {
        const int buf = t & 1;
        const bool more = (t + 1 < nTiles);
        if (more) fetch((t + 1) * BKK, pa0, pa1, pb0, pb1);

        const float* as = As[buf];
        const float* bs = Bs[buf];
        #pragma unroll
        for (int kk = 0; kk < BKK; kk++) {
            const float* ar = as + kk * LDSM;
            const float* br = bs + kk * LDSM;
            float af[8];
            *(float4*)(af)     = *(const float4*)(ar + r0);
            *(float4*)(af + 4) = *(const float4*)(ar + r0 + 64);
            unsigned long long b2[4];
            b2[0] = *(const unsigned long long*)(br + c0);
            b2[1] = *(const unsigned long long*)(br + c0 + 2);
            b2[2] = *(const unsigned long long*)(br + c0 + 64);
            b2[3] = *(const unsigned long long*)(br + c0 + 66);
            #pragma unroll
            for (int i = 0; i < 8; i++) {
                unsigned long long a2;
                asm("mov.b64 %0, {%1, %1};" : "=l"(a2) : "r"(__float_as_uint(af[i])));
                #pragma unroll
                for (int j = 0; j < 4; j++)
                    asm("fma.rn.f32x2 %0, %1, %2, %0;"
                        : "+l"(acc2[i][j]) : "l"(a2), "l"(b2[j]));
            }
        }
        __syncthreads();
        if (more) {
            store(buf ^ 1, pa0, pa1, pb0, pb1);
            __syncthreads();
        }
    }

    // ---- epilogue: bias + store (float4; Nc and c0 are multiples of 4) ----
    #pragma unroll
    for (int i = 0; i < 8; i++) {
        int row = bm + ((i < 4) ? (r0 + i) : (r0 + 64 + i - 4));
        if (row >= M) continue;
        #pragma unroll
        for (int jq = 0; jq < 2; jq++) {
            int col = bn + c0 + jq * 64;
            if (col >= Nc) continue;
            float2 p0 = *(float2*)&acc2[i][2 * jq];
            float2 p1 = *(float2*)&acc2[i][2 * jq + 1];
            float4 v = make_float4(p0.x, p0.y, p1.x, p1.y);
            if (bias) {
                v.x += bias[col]; v.y += bias[col + 1];
                v.z += bias[col + 2]; v.w += bias[col + 3];
            }
            *(float4*)(Cc + (long)row * Nc + col) = v;
        }
    }
}

// ---------------- fused init: all zero/neg-inf fills in one launch ----------------
#define INIT_E1 (NN*NHEADS)                       // emax1  <- -1e30
#define INIT_D1 (NN*NHEADS)                       // den1   <- 0
#define INIT_AG (NN*NHEADS*CC1)                   // agg1   <- 0
#define INIT_O  (NN*CC2)                          // out    <- 0
#define INIT_TOTAL (INIT_E1 + INIT_D1 + INIT_AG + NN + NN + INIT_O + 2)
__global__ void init_all_k(float* emax1, float* den1, float* agg1,
                           float* emax2, float* den2, float* out, float* acc) {
    int i = blockIdx.x * blockDim.x + threadIdx.x;
    if (i >= INIT_TOTAL) return;
    if (i < INIT_E1) { emax1[i] = -1e30f; return; }
    i -= INIT_E1;
    if (i < INIT_D1) { den1[i] = 0.f; return; }
    i -= INIT_D1;
    if (i < INIT_AG) { agg1[i] = 0.f; return; }
    i -= INIT_AG;
    if (i < NN) { emax2[i] = -1e30f; return; }
    i -= NN;
    if (i < NN) { den2[i] = 0.f; return; }
    i -= NN;
    if (i < INIT_O) { out[i] = 0.f; return; }
    i -= INIT_O;
    acc[i] = 0.f;
}

// ---------------- elementwise / utility kernels ----------------
__global__ void copy_k(float* dst, const float* src, int n) {
    int i = blockIdx.x * blockDim.x + threadIdx.x;
    if (i < n) dst[i] = src[i];
}
// tok[t*NT+n] = gnf[n*T+t]  (xe = emb[gnf].transpose(1,0,2))
__global__ void tok_k(int* tok, const int* gnf) {
    int i = blockIdx.x * blockDim.x + threadIdx.x;
    if (i >= MM0) return;
    int t = i / NTV, n = i % NTV;
    tok[i] = gnf[n * TT + t];
}
// torch GRU gate math (gate order r,z,n), in-place h update
__global__ void gru_gate_k(const float* __restrict__ GI, const float* __restrict__ GH,
                           float* __restrict__ h, float* __restrict__ o) {
    int idx = blockIdx.x * blockDim.x + threadIdx.x;
    if (idx >= NTV * HH) return;
    int n = idx >> 8, j = idx & 255;
    const float* gi = GI + (long)n * GG;
    const float* gh = GH + (long)n * GG;
    float r = sigmoidf_(gi[j] + gh[j]);
    float z = sigmoidf_(gi[HH + j] + gh[HH + j]);
    float nn = tanhf(gi[2 * HH + j] + r * gh[2 * HH + j]);
    float hv = h[idx];
    float hn = (1.f - z) * nn + z * hv;
    h[idx] = hn;
    if (o) o[idx] = hn;
}
// z = mu + exp(0.5*lv)*eps ; accumulate KL sum
__global__ void vae_z_kl_k(const float* mu, const float* lv, const float* eps,
                           float* z, float* acc) {
    int i = blockIdx.x * blockDim.x + threadIdx.x;
    float term = 0.f;
    if (i < NUV * ZZ) {
        float m = mu[i], l = lv[i];
        z[i] = m + expf(0.5f * l) * eps[i];
        term = 1.f + l - m * m - expf(l);
    }
    block_reduce_add(term, &acc[0]);
}
__global__ void rec_loss_k(const float* rec, const float* uf, float* acc) {
    int i = blockIdx.x * blockDim.x + threadIdx.x;
    float term = 0.f;
    if (i < NUV * FF) {
        float d = rec[i] - uf[i];
        term = d * d;
    }
    block_reduce_add(term, &acc[1]);
}
// x_in = concat(hn[:B], z, hn[B:])
__global__ void assemble_k(const float* hn, const float* z, float* xin) {
    int i = blockIdx.x * blockDim.x + threadIdx.x;
    if (i >= NN * HH) return;
    int row = i >> 8, j = i & 255;
    float v;
    if (row < BB)            v = hn[row * HH + j];
    else if (row < BB + NUV) v = z[(row - BB) * ZZ + j];
    else                     v = hn[(row - NUV) * HH + j];
    xin[i] = v;
}
// per-node attention dot products
__global__ void asad_k(const float* __restrict__ xp, const float* __restrict__ a_src,
                       const float* __restrict__ a_dst, float* as_n, float* ad_n,
                       int heads, int C) {
    int idx = blockIdx.x * blockDim.x + threadIdx.x;
    if (idx >= NN * heads) return;
    int node = idx / heads, h = idx % heads;
    const float* row = xp + (long)node * heads * C + h * C;
    float s = 0.f, d = 0.f;
    for (int c = 0; c < C; c++) { float v = row[c]; s += v * a_src[h * C + c]; d += v * a_dst[h * C + c]; }
    as_n[idx] = s; ad_n[idx] = d;
}
__device__ __forceinline__ void edge_sd(int e, const int* ei, int& s, int& d) {
    if (e < EE) { s = ei[e]; d = ei[EE + e]; } else { s = d = e - EE; }
}
// pass A: logits + segment max over dst
__global__ void edgeA_k(const float* as_n, const float* ad_n, const int* ei,
                        float* ebuf, float* emax, int heads) {
    int idx = blockIdx.x * blockDim.x + threadIdx.x;
    if (idx >= ETOT * heads) return;
    int e = idx / heads, h = idx % heads;
    int s, d; edge_sd(e, ei, s, d);
    float v = as_n[s * heads + h] + ad_n[d * heads + h];
    v = v > 0.f ? v : 0.2f * v;  // leaky_relu(0.2)
    ebuf[idx] = v;
    atomicMaxFloat(&emax[d * heads + h], v);
}
// pass B: exp + segment sum
__global__ void edgeB_k(const int* ei, float* ebuf, const float* emax,
                        float* den, int heads) {
    int idx = blockIdx.x * blockDim.x + threadIdx.x;
    if (idx >= ETOT * heads) return;
    int e = idx / heads, h = idx % heads;
    int s, d; edge_sd(e, ei, s, d);
    float ee = expf(ebuf[idx] - emax[d * heads + h]);
    ebuf[idx] = ee;
    atomicAdd(&den[d * heads + h], ee);
}
// pass C: weighted scatter (float4 loads, vec4 reduction stores)
__global__ void edgeC_k(const float* __restrict__ xp, const float* __restrict__ ebuf,
                        const float* __restrict__ den, const int* __restrict__ ei,
                        float* __restrict__ agg, int heads, int C) {
    int Q = heads * C / 4;
    long idx = (long)blockIdx.x * blockDim.x + threadIdx.x;
    if (idx >= (long)ETOT * Q) return;
    int e = (int)(idx / Q), q = (int)(idx % Q);
    int c0 = q * 4, h = c0 / C;
    int s, d; edge_sd(e, ei, s, d);
    float al = ebuf[e * heads + h] / den[d * heads + h];
    const float4 v = *(const float4*)(xp + (long)s * heads * C + c0);
    float* dst = agg + (long)d * heads * C + c0;
    redAdd4(dst, v.x * al, v.y * al, v.z * al, v.w * al);
}
__global__ void addbias_k(float* x, const float* b, int cols, int total) {
    int i = blockIdx.x * blockDim.x + threadIdx.x;
    if (i < total) x[i] += b[i % cols];
}
__global__ void scalars_k(const float* acc, float* out, int os) {
    if (threadIdx.x == 0) {
        out[os - 2] = -0.5f * acc[0] / (float)NUV;           // kl_loss
        out[os - 1] = acc[1] / ((float)NUV * (float)FF);     // rec_loss
    }
}

// ---------------- host orchestration ----------------
static inline int cd(long a, long b) { return (int)((a + b - 1) / b); }

extern "C" void kernel_launch(void* const* d_in, const int* in_sizes, int n_in,
                              void* d_out, int out_size) {
    (void)in_sizes; (void)n_in;
    const float* user_feats = (const float*)d_in[1];
    const int*   gnf  = (const int*)d_in[2];
    const int*   ei   = (const int*)d_in[3];
    const float* emb  = (const float*)d_in[4];
    const float* w_ih0 = (const float*)d_in[5],  *w_hh0 = (const float*)d_in[6];
    const float* b_ih0 = (const float*)d_in[7],  *b_hh0 = (const float*)d_in[8];
    const float* w_ih1 = (const float*)d_in[9],  *w_hh1 = (const float*)d_in[10];
    const float* b_ih1 = (const float*)d_in[11], *b_hh1 = (const float*)d_in[12];
    const float* h0    = (const float*)d_in[13];
    const float* w_mu  = (const float*)d_in[14], *b_mu  = (const float*)d_in[15];
    const float* w_lv  = (const float*)d_in[16], *b_lv  = (const float*)d_in[17];
    const float* w_dec = (const float*)d_in[18], *b_dec = (const float*)d_in[19];
    const float* veps  = (const float*)d_in[20];
    const float* w1 = (const float*)d_in[21], *a_src1 = (const float*)d_in[22];
    const float* a_dst1 = (const float*)d_in[23], *b1 = (const float*)d_in[24];
    const float* w2 = (const float*)d_in[25], *a_src2 = (const float*)d_in[26];
    const float* a_dst2 = (const float*)d_in[27], *b2 = (const float*)d_in[28];
    float* out = (float*)d_out;

    float *GI0, *GI1, *OUT0, *GH, *h0b, *h1b, *mu, *lv, *z, *rec, *xin;
    float *xp1, *as1, *ad1, *e1, *emax1, *den1, *agg1;
    float *xp2, *as2, *ad2, *e2, *emax2, *den2, *acc;
    int* tok;
    cudaGetSymbolAddress((void**)&GI0, g_GI0);
    cudaGetSymbolAddress((void**)&GI1, g_GI1);
    cudaGetSymbolAddress((void**)&OUT0, g_OUT0);
    cudaGetSymbolAddress((void**)&GH, g_GH);
    cudaGetSymbolAddress((void**)&h0b, g_h0);
    cudaGetSymbolAddress((void**)&h1b, g_h1);
    cudaGetSymbolAddress((void**)&tok, g_tok);
    cudaGetSymbolAddress((void**)&mu, g_mu);
    cudaGetSymbolAddress((void**)&lv, g_lv);
    cudaGetSymbolAddress((void**)&z, g_zbuf);
    cudaGetSymbolAddress((void**)&rec, g_rec);
    cudaGetSymbolAddress((void**)&xin, g_xin);
    cudaGetSymbolAddress((void**)&xp1, g_xp1);
    cudaGetSymbolAddress((void**)&as1, g_as1);
    cudaGetSymbolAddress((void**)&ad1, g_ad1);
    cudaGetSymbolAddress((void**)&e1, g_e1);
    cudaGetSymbolAddress((void**)&emax1, g_emax1);
    cudaGetSymbolAddress((void**)&den1, g_den1);
    cudaGetSymbolAddress((void**)&agg1, g_agg1);
    cudaGetSymbolAddress((void**)&xp2, g_xp2);
    cudaGetSymbolAddress((void**)&as2, g_as2);
    cudaGetSymbolAddress((void**)&ad2, g_ad2);
    cudaGetSymbolAddress((void**)&e2, g_e2);
    cudaGetSymbolAddress((void**)&emax2, g_emax2);
    cudaGetSymbolAddress((void**)&den2, g_den2);
    cudaGetSymbolAddress((void**)&acc, g_acc);

    const dim3 blk(256);

    // ---- per-launch init (determinism) ----
    init_all_k<<<cd(INIT_TOTAL, 256), 256>>>(emax1, den1, agg1, emax2, den2, out, acc);
    copy_k<<<cd(NTV * HH, 256), 256>>>(h0b, h0, NTV * HH);
    copy_k<<<cd(NTV * HH, 256), 256>>>(h1b, h0 + NTV * HH, NTV * HH);
    tok_k<<<cd(MM0, 256), 256>>>(tok, gnf);

    // ---- GRU layer 0: batched input projection (gather fused) ----
    {
        dim3 g(cd(GG, 128), cd(MM0, 128));
        gemm_k<true, true><<<g, blk>>>(emb, w_ih0, b_ih0, GI0, MM0, GG, DD, tok);
    }
    for (int t = 0; t < TT; t++) {
        dim3 g(cd(GG, 128), cd(NTV, 128));
        gemm_k<true, false><<<g, blk>>>(h0b, w_hh0, b_hh0, GH, NTV, GG, HH, nullptr);
        gru_gate_k<<<cd(NTV * HH, 256), 256>>>(GI0 + (size_t)t * NTV * GG, GH, h0b,
                                               OUT0 + (size_t)t * NTV * HH);
    }
    // ---- GRU layer 1: batched input projection from OUT0 ----
    {
        dim3 g(cd(GG, 128), cd(MM0, 128));
        gemm_k<true, false><<<g, blk>>>(OUT0, w_ih1, b_ih1, GI1, MM0, GG, HH, nullptr);
    }
    for (int t = 0; t < TT; t++) {
        dim3 g(cd(GG, 128), cd(NTV, 128));
        gemm_k<true, false><<<g, blk>>>(h1b, w_hh1, b_hh1, GH, NTV, GG, HH, nullptr);
        gru_gate_k<<<cd(NTV * HH, 256), 256>>>(GI1 + (size_t)t * NTV * GG, GH, h1b, nullptr);
    }

    // ---- VAE ----
    {
        dim3 g(cd(ZZ, 128), cd(NUV, 128));
        gemm_k<true, false><<<g, blk>>>(user_feats, w_mu, b_mu, mu, NUV, ZZ, FF, nullptr);
        gemm_k<true, false><<<g, blk>>>(user_feats, w_lv, b_lv, lv, NUV, ZZ, FF, nullptr);
    }
    vae_z_kl_k<<<cd(NUV * ZZ, 256), 256>>>(mu, lv, veps, z, acc);
    {
        dim3 g(cd(FF, 128), cd(NUV, 128));
        gemm_k<true, false><<<g, blk>>>(z, w_dec, b_dec, rec, NUV, FF, ZZ, nullptr);
    }
    rec_loss_k<<<cd(NUV * FF, 256), 256>>>(rec, user_feats, acc);

    // ---- node feature assembly ----
    assemble_k<<<cd(NN * HH, 256), 256>>>(h1b, z, xin);

    // ---- GAT layer 1 (8 heads x 64, concat) ----
    {
        dim3 g(cd(NHEADS * CC1, 128), cd(NN, 128));
        gemm_k<false, false><<<g, blk>>>(xin, w1, nullptr, xp1, NN, NHEADS * CC1, HH, nullptr);
    }
    asad_k<<<cd(NN * NHEADS, 256), 256>>>(xp1, a_src1, a_dst1, as1, ad1, NHEADS, CC1);
    edgeA_k<<<cd((long)ETOT * NHEADS, 256), 256>>>(as1, ad1, ei, e1, emax1, NHEADS);
    edgeB_k<<<cd((long)ETOT * NHEADS, 256), 256>>>(ei, e1, emax1, den1, NHEADS);
    edgeC_k<<<cd((long)ETOT * NHEADS * CC1 / 4, 256), 256>>>(xp1, e1, den1, ei, agg1, NHEADS, CC1);
    addbias_k<<<cd(NN * NHEADS * CC1, 256), 256>>>(agg1, b1, NHEADS * CC1, NN * NHEADS * CC1);

    // ---- GAT layer 2 (1 head x 100, mean == identity) ----
    {
        dim3 g(cd(CC2, 128), cd(NN, 128));
        gemm_k<false, false><<<g, blk>>>(agg1, w2, nullptr, xp2, NN, CC2, NHEADS * CC1, nullptr);
    }
    asad_k<<<cd(NN, 256), 256>>>(xp2, a_src2, a_dst2, as2, ad2, 1, CC2);
    edgeA_k<<<cd(ETOT, 256), 256>>>(as2, ad2, ei, e2, emax2, 1);
    edgeB_k<<<cd(ETOT, 256), 256>>>(ei, e2, emax2, den2, 1);
    edgeC_k<<<cd((long)ETOT * CC2 / 4, 256), 256>>>(xp2, e2, den2, ei, out, 1, CC2);
    addbias_k<<<cd(NN * CC2, 256), 256>>>(out, b2, CC2, NN * CC2);

    // ---- scalar losses ----
    scalars_k<<<1, 32>>>(acc, out, out_size);
}

// round 8
// speedup vs baseline: 2.5846x; 1.4720x over previous
#include <cuda_runtime.h>
#include <cuda_bf16.h>
#include <cstddef>

// ---------------- problem dims ----------------
#define TT 24          // seq len
#define DD 300         // glove dim
#define HH 256         // GRU hidden / z dim
#define NTV 6000       // tweet nodes
#define NUV 4000       // user nodes
#define NN 10000       // total nodes
#define FF 512         // user feat size
#define ZZ 256         // z dim
#define EE 80000       // edges
#define BB 2000        // batch (source tweets)
#define CC1 64         // GAT1 out channels
#define CC2 100        // GAT2 out channels
#define NHEADS 8
#define GG 768         // 3*H
#define MM0 (TT*NTV)   // 144000
#define ETOT (EE+NN)   // 90000 (edges + self loops)

// ---------------- scratch (device globals; no allocation allowed) ----------------
__device__ float g_GI0[(size_t)MM0*GG];
__device__ float g_GI1[(size_t)MM0*GG];
__device__ float g_OUT0[(size_t)MM0*HH];
__device__ float g_GH[NTV*GG];
__device__ float g_h0[NTV*HH];
__device__ float g_h1[NTV*HH];
__device__ int   g_tok[MM0];
__device__ float g_mu[NUV*ZZ];
__device__ float g_lv[NUV*ZZ];
__device__ float g_zbuf[NUV*ZZ];
__device__ float g_rec[NUV*FF];
__device__ float g_xin[NN*HH];
__device__ float g_xp1[NN*NHEADS*CC1];
__device__ float g_as1[NN*NHEADS];
__device__ float g_ad1[NN*NHEADS];
__device__ float g_e1[ETOT*NHEADS];
__device__ float g_emax1[NN*NHEADS];
__device__ float g_den1[NN*NHEADS];
__device__ float g_agg1[NN*NHEADS*CC1];
__device__ float g_xp2[NN*CC2];
__device__ float g_as2[NN];
__device__ float g_ad2[NN];
__device__ float g_e2[ETOT];
__device__ float g_emax2[NN];
__device__ float g_den2[NN];
__device__ float g_acc[2];

// ---------------- small helpers ----------------
__device__ __forceinline__ float sigmoidf_(float x) { return 1.f / (1.f + expf(-x)); }

__device__ __forceinline__ void atomicMaxFloat(float* addr, float val) {
    int old = __float_as_int(*addr);
    while (__int_as_float(old) < val) {
        int assumed = old;
        old = atomicCAS((int*)addr, assumed, __float_as_int(val));
        if (old == assumed) break;
    }
}

__device__ __forceinline__ void redAdd4(float* addr, float a, float b, float c, float d) {
    asm volatile("red.global.add.v4.f32 [%0], {%1, %2, %3, %4};"
                 :: "l"(addr), "f"(a), "f"(b), "f"(c), "f"(d) : "memory");
}

__device__ __forceinline__ void block_reduce_add(float v, float* target) {
    #pragma unroll
    for (int o = 16; o > 0; o >>= 1) v += __shfl_down_sync(0xffffffffu, v, o);
    __shared__ float s[16];
    int lane = threadIdx.x & 31, w = threadIdx.x >> 5;
    if (lane == 0) s[w] = v;
    __syncthreads();
    if (w == 0) {
        v = (lane < (int)(blockDim.x >> 5)) ? s[lane] : 0.f;
        #pragma unroll
        for (int o = 8; o > 0; o >>= 1) v += __shfl_down_sync(0xffffffffu, v, o);
        if (lane == 0) atomicAdd(target, v);
    }
}

// ================= GEMM v4: bf16 3-term split on tensor cores =================
// C = A @ op(B) (+bias), fp32 in/out, internally a_hi*b_hi + a_hi*b_lo + a_lo*b_hi
// BT=true : B is (N,K) row-major -> C = A @ B^T
// BT=false: B is (K,N) row-major -> C = A @ B
// GATHER  : A row m is A[rowidx[m]]
// Block: 512 threads (16 warps, 4x4 grid, 32x32 warp tile), tile 128x128x32.
#define LDB 40                       // bf16 elems per smem row (32 + 8 pad)
#define LDC 136                      // fp32 stride for epilogue staging
#define GTILE (128*LDB)              // elems per smem sub-tile
#define GSMEM_BYTES (8*GTILE*2)      // 81920 B (2 bufs x {Ahi,Alo,Bhi,Blo})

__device__ __forceinline__ void ldmx4(unsigned* d, const unsigned short* p) {
    unsigned addr = (unsigned)__cvta_generic_to_shared(p);
    asm volatile("ldmatrix.sync.aligned.m8n8.x4.shared.b16 {%0,%1,%2,%3}, [%4];"
        : "=r"(d[0]), "=r"(d[1]), "=r"(d[2]), "=r"(d[3]) : "r"(addr));
}
__device__ __forceinline__ void mma_bf16(float* d, const unsigned* a, unsigned b0, unsigned b1) {
    asm volatile("mma.sync.aligned.m16n8k16.row.col.f32.bf16.bf16.f32 "
        "{%0,%1,%2,%3}, {%4,%5,%6,%7}, {%8,%9}, {%0,%1,%2,%3};"
        : "+f"(d[0]), "+f"(d[1]), "+f"(d[2]), "+f"(d[3])
        : "r"(a[0]), "r"(a[1]), "r"(a[2]), "r"(a[3]), "r"(b0), "r"(b1));
}
__device__ __forceinline__ void cvt_store8(unsigned short* hi, unsigned short* lo,
                                           int off, float4 v) {
    ushort4 h, l;
    __nv_bfloat16 b;
    b = __float2bfloat16(v.x); h.x = __bfloat16_as_ushort(b);
    l.x = __bfloat16_as_ushort(__float2bfloat16(v.x - __bfloat162float(b)));
    b = __float2bfloat16(v.y); h.y = __bfloat16_as_ushort(b);
    l.y = __bfloat16_as_ushort(__float2bfloat16(v.y - __bfloat162float(b)));
    b = __float2bfloat16(v.z); h.z = __bfloat16_as_ushort(b);
    l.z = __bfloat16_as_ushort(__float2bfloat16(v.z - __bfloat162float(b)));
    b = __float2bfloat16(v.w); h.w = __bfloat16_as_ushort(b);
    l.w = __bfloat16_as_ushort(__float2bfloat16(v.w - __bfloat162float(b)));
    *(ushort4*)(hi + off) = h;
    *(ushort4*)(lo + off) = l;
}

template<bool BT, bool GATHER>
__global__ __launch_bounds__(512, 1)
void gemm_k(const float* __restrict__ A, const float* __restrict__ Bm,
            const float* __restrict__ bias, float* __restrict__ Cc,
            int M, int Nc, int K, const int* __restrict__ rowidx)
{
    extern __shared__ unsigned short SMEM[];
    __shared__ int ridx[128];

    const int tid = threadIdx.x;
    const int lane = tid & 31, wid = tid >> 5;
    const int wm = wid & 3, wn = wid >> 2;   // 4x4 warps, each 32x32
    const int bm = blockIdx.y * 128, bn = blockIdx.x * 128;

    if (tid < 128) {
        int r = bm + tid;
        ridx[tid] = (r < M) ? (GATHER ? rowidx[r] : r) : -1;
    }
    __syncthreads();

    float acc[2][4][4];
    #pragma unroll
    for (int i = 0; i < 2; i++)
        #pragma unroll
        for (int j = 0; j < 4; j++)
            #pragma unroll
            for (int q = 0; q < 4; q++) acc[i][j][q] = 0.f;

    // loader coords
    const int a_r = tid >> 3;          // 0..63 (+64 for second chunk)
    const int a_k = (tid & 7) << 2;    // 0,4,...,28
    const int b_n = tid & 127;         // non-BT: n within tile
    const int b_k = (tid >> 7) << 2;   // 0,4,8,12 (+16 for second chunk)

    float4 fa0, fa1, fb0, fb1;

    auto FETCH = [&](int kt) {
        const float4 z4 = make_float4(0.f, 0.f, 0.f, 0.f);
        int gr = ridx[a_r];
        fa0 = (gr >= 0 && kt + a_k < K) ? *(const float4*)(A + (size_t)gr * K + kt + a_k) : z4;
        gr = ridx[a_r + 64];
        fa1 = (gr >= 0 && kt + a_k < K) ? *(const float4*)(A + (size_t)gr * K + kt + a_k) : z4;
        if (BT) {
            int n = bn + a_r;
            fb0 = (n < Nc && kt + a_k < K) ? *(const float4*)(Bm + (size_t)n * K + kt + a_k) : z4;
            n = bn + a_r + 64;
            fb1 = (n < Nc && kt + a_k < K) ? *(const float4*)(Bm + (size_t)n * K + kt + a_k) : z4;
        } else {
            bool nok = (bn + b_n) < Nc;
            float t0[4], t1[4];
            #pragma unroll
            for (int i = 0; i < 4; i++) {
                int k0 = kt + b_k + i, k1 = kt + b_k + 16 + i;
                t0[i] = (nok && k0 < K) ? Bm[(size_t)k0 * Nc + bn + b_n] : 0.f;
                t1[i] = (nok && k1 < K) ? Bm[(size_t)k1 * Nc + bn + b_n] : 0.f;
            }
            fb0 = make_float4(t0[0], t0[1], t0[2], t0[3]);
            fb1 = make_float4(t1[0], t1[1], t1[2], t1[3]);
        }
    };
    auto STORE = [&](int buf) {
        unsigned short* Ah = SMEM + (buf * 4 + 0) * GTILE;
        unsigned short* Al = SMEM + (buf * 4 + 1) * GTILE;
        unsigned short* Bh = SMEM + (buf * 4 + 2) * GTILE;
        unsigned short* Bl = SMEM + (buf * 4 + 3) * GTILE;
        cvt_store8(Ah, Al, a_r * LDB + a_k, fa0);
        cvt_store8(Ah, Al, (a_r + 64) * LDB + a_k, fa1);
        if (BT) {
            cvt_store8(Bh, Bl, a_r * LDB + a_k, fb0);
            cvt_store8(Bh, Bl, (a_r + 64) * LDB + a_k, fb1);
        } else {
            cvt_store8(Bh, Bl, b_n * LDB + b_k, fb0);
            cvt_store8(Bh, Bl, b_n * LDB + b_k + 16, fb1);
        }
    };

    const int nT = (K + 31) >> 5;
    FETCH(0); STORE(0); __syncthreads();

    const int lr = lane & 15, lko = (lane >> 4) << 3;

    for (int t = 0; t < nT; t++) {
        const int buf = t & 1;
        if (t + 1 < nT) FETCH((t + 1) << 5);
        const unsigned short* Ah = SMEM + (buf * 4 + 0) * GTILE;
        const unsigned short* Al = SMEM + (buf * 4 + 1) * GTILE;
        const unsigned short* Bh = SMEM + (buf * 4 + 2) * GTILE;
        const unsigned short* Bl = SMEM + (buf * 4 + 3) * GTILE;
        #pragma unroll
        for (int kc = 0; kc < 32; kc += 16) {
            unsigned ah[2][4], al[2][4];
            #pragma unroll
            for (int mf = 0; mf < 2; mf++) {
                int off = (wm * 32 + mf * 16 + lr) * LDB + kc + lko;
                ldmx4(ah[mf], Ah + off);
                ldmx4(al[mf], Al + off);
            }
            #pragma unroll
            for (int np = 0; np < 2; np++) {
                int off = (wn * 32 + np * 16 + lr) * LDB + kc + lko;
                unsigned bh[4], bl[4];
                ldmx4(bh, Bh + off);
                ldmx4(bl, Bl + off);
                #pragma unroll
                for (int mf = 0; mf < 2; mf++)
                    #pragma unroll
                    for (int s = 0; s < 2; s++) {
                        float* d = acc[mf][np * 2 + s];
                        mma_bf16(d, ah[mf], bh[s], bh[s + 2]);  // hi*hi
                        mma_bf16(d, ah[mf], bl[s], bl[s + 2]);  // hi*lo
                        mma_bf16(d, al[mf], bh[s], bh[s + 2]);  // lo*hi
                    }
            }
        }
        if (t + 1 < nT) STORE(buf ^ 1);
        __syncthreads();
    }

    // ---- epilogue: stage C through smem for coalesced gmem stores ----
    float* Cs = (float*)SMEM;
    #pragma unroll
    for (int mf = 0; mf < 2; mf++)
        #pragma unroll
        for (int nf = 0; nf < 4; nf++) {
            int r = wm * 32 + mf * 16 + (lane >> 2);
            int c = wn * 32 + nf * 8 + (lane & 3) * 2;
            *(float2*)&Cs[r * LDC + c]       = make_float2(acc[mf][nf][0], acc[mf][nf][1]);
            *(float2*)&Cs[(r + 8) * LDC + c] = make_float2(acc[mf][nf][2], acc[mf][nf][3]);
        }
    __syncthreads();
    #pragma unroll
    for (int q = 0; q < 8; q++) {
        int idx = q * 512 + tid;
        int row = idx >> 5, c4 = (idx & 31) << 2;
        int grow = bm + row, gcol = bn + c4;
        if (grow < M && gcol < Nc) {
            float4 v = *(float4*)&Cs[row * LDC + c4];
            if (bias) {
                v.x += bias[gcol];     v.y += bias[gcol + 1];
                v.z += bias[gcol + 2]; v.w += bias[gcol + 3];
            }
            *(float4*)(Cc + (size_t)grow * Nc + gcol) = v;
        }
    }
}

// ---------------- fused init: all zero/neg-inf fills in one launch ----------------
#define INIT_E1 (NN*NHEADS)
#define INIT_D1 (NN*NHEADS)
#define INIT_AG (NN*NHEADS*CC1)
#define INIT_O  (NN*CC2)
#define INIT_TOTAL (INIT_E1 + INIT_D1 + INIT_AG + NN + NN + INIT_O + 2)
__global__ void init_all_k(float* emax1, float* den1, float* agg1,
                           float* emax2, float* den2, float* out, float* acc) {
    int i = blockIdx.x * blockDim.x + threadIdx.x;
    if (i >= INIT_TOTAL) return;
    if (i < INIT_E1) { emax1[i] = -1e30f; return; }
    i -= INIT_E1;
    if (i < INIT_D1) { den1[i] = 0.f; return; }
    i -= INIT_D1;
    if (i < INIT_AG) { agg1[i] = 0.f; return; }
    i -= INIT_AG;
    if (i < NN) { emax2[i] = -1e30f; return; }
    i -= NN;
    if (i < NN) { den2[i] = 0.f; return; }
    i -= NN;
    if (i < INIT_O) { out[i] = 0.f; return; }
    i -= INIT_O;
    acc[i] = 0.f;
}

// ---------------- elementwise / utility kernels ----------------
__global__ void copy_k(float* dst, const float* src, int n) {
    int i = blockIdx.x * blockDim.x + threadIdx.x;
    if (i < n) dst[i] = src[i];
}
__global__ void tok_k(int* tok, const int* gnf) {
    int i = blockIdx.x * blockDim.x + threadIdx.x;
    if (i >= MM0) return;
    int t = i / NTV, n = i % NTV;
    tok[i] = gnf[n * TT + t];
}
__global__ void gru_gate_k(const float* __restrict__ GI, const float* __restrict__ GH,
                           float* __restrict__ h, float* __restrict__ o) {
    int idx = blockIdx.x * blockDim.x + threadIdx.x;
    if (idx >= NTV * HH) return;
    int n = idx >> 8, j = idx & 255;
    const float* gi = GI + (long)n * GG;
    const float* gh = GH + (long)n * GG;
    float r = sigmoidf_(gi[j] + gh[j]);
    float z = sigmoidf_(gi[HH + j] + gh[HH + j]);
    float nn = tanhf(gi[2 * HH + j] + r * gh[2 * HH + j]);
    float hv = h[idx];
    float hn = (1.f - z) * nn + z * hv;
    h[idx] = hn;
    if (o) o[idx] = hn;
}
__global__ void vae_z_kl_k(const float* mu, const float* lv, const float* eps,
                           float* z, float* acc) {
    int i = blockIdx.x * blockDim.x + threadIdx.x;
    float term = 0.f;
    if (i < NUV * ZZ) {
        float m = mu[i], l = lv[i];
        z[i] = m + expf(0.5f * l) * eps[i];
        term = 1.f + l - m * m - expf(l);
    }
    block_reduce_add(term, &acc[0]);
}
__global__ void rec_loss_k(const float* rec, const float* uf, float* acc) {
    int i = blockIdx.x * blockDim.x + threadIdx.x;
    float term = 0.f;
    if (i < NUV * FF) {
        float d = rec[i] - uf[i];
        term = d * d;
    }
    block_reduce_add(term, &acc[1]);
}
__global__ void assemble_k(const float* hn, const float* z, float* xin) {
    int i = blockIdx.x * blockDim.x + threadIdx.x;
    if (i >= NN * HH) return;
    int row = i >> 8, j = i & 255;
    float v;
    if (row < BB)            v = hn[row * HH + j];
    else if (row < BB + NUV) v = z[(row - BB) * ZZ + j];
    else                     v = hn[(row - NUV) * HH + j];
    xin[i] = v;
}
__global__ void asad_k(const float* __restrict__ xp, const float* __restrict__ a_src,
                       const float* __restrict__ a_dst, float* as_n, float* ad_n,
                       int heads, int C) {
    int idx = blockIdx.x * blockDim.x + threadIdx.x;
    if (idx >= NN * heads) return;
    int node = idx / heads, h = idx % heads;
    const float* row = xp + (long)node * heads * C + h * C;
    float s = 0.f, d = 0.f;
    for (int c = 0; c < C; c++) { float v = row[c]; s += v * a_src[h * C + c]; d += v * a_dst[h * C + c]; }
    as_n[idx] = s; ad_n[idx] = d;
}
__device__ __forceinline__ void edge_sd(int e, const int* ei, int& s, int& d) {
    if (e < EE) { s = ei[e]; d = ei[EE + e]; } else { s = d = e - EE; }
}
__global__ void edgeA_k(const float* as_n, const float* ad_n, const int* ei,
                        float* ebuf, float* emax, int heads) {
    int idx = blockIdx.x * blockDim.x + threadIdx.x;
    if (idx >= ETOT * heads) return;
    int e = idx / heads, h = idx % heads;
    int s, d; edge_sd(e, ei, s, d);
    float v = as_n[s * heads + h] + ad_n[d * heads + h];
    v = v > 0.f ? v : 0.2f * v;
    ebuf[idx] = v;
    atomicMaxFloat(&emax[d * heads + h], v);
}
__global__ void edgeB_k(const int* ei, float* ebuf, const float* emax,
                        float* den, int heads) {
    int idx = blockIdx.x * blockDim.x + threadIdx.x;
    if (idx >= ETOT * heads) return;
    int e = idx / heads, h = idx % heads;
    int s, d; edge_sd(e, ei, s, d);
    float ee = expf(ebuf[idx] - emax[d * heads + h]);
    ebuf[idx] = ee;
    atomicAdd(&den[d * heads + h], ee);
}
__global__ void edgeC_k(const float* __restrict__ xp, const float* __restrict__ ebuf,
                        const float* __restrict__ den, const int* __restrict__ ei,
                        float* __restrict__ agg, int heads, int C) {
    int Q = heads * C / 4;
    long idx = (long)blockIdx.x * blockDim.x + threadIdx.x;
    if (idx >= (long)ETOT * Q) return;
    int e = (int)(idx / Q), q = (int)(idx % Q);
    int c0 = q * 4, h = c0 / C;
    int s, d; edge_sd(e, ei, s, d);
    float al = ebuf[e * heads + h] / den[d * heads + h];
    const float4 v = *(const float4*)(xp + (long)s * heads * C + c0);
    float* dst = agg + (long)d * heads * C + c0;
    redAdd4(dst, v.x * al, v.y * al, v.z * al, v.w * al);
}
__global__ void addbias_k(float* x, const float* b, int cols, int total) {
    int i = blockIdx.x * blockDim.x + threadIdx.x;
    if (i < total) x[i] += b[i % cols];
}
__global__ void scalars_k(const float* acc, float* out, int os) {
    if (threadIdx.x == 0) {
        out[os - 2] = -0.5f * acc[0] / (float)NUV;
        out[os - 1] = acc[1] / ((float)NUV * (float)FF);
    }
}

// ---------------- host orchestration ----------------
static inline int cd(long a, long b) { return (int)((a + b - 1) / b); }

extern "C" void kernel_launch(void* const* d_in, const int* in_sizes, int n_in,
                              void* d_out, int out_size) {
    (void)in_sizes; (void)n_in;
    const float* user_feats = (const float*)d_in[1];
    const int*   gnf  = (const int*)d_in[2];
    const int*   ei   = (const int*)d_in[3];
    const float* emb  = (const float*)d_in[4];
    const float* w_ih0 = (const float*)d_in[5],  *w_hh0 = (const float*)d_in[6];
    const float* b_ih0 = (const float*)d_in[7],  *b_hh0 = (const float*)d_in[8];
    const float* w_ih1 = (const float*)d_in[9],  *w_hh1 = (const float*)d_in[10];
    const float* b_ih1 = (const float*)d_in[11], *b_hh1 = (const float*)d_in[12];
    const float* h0    = (const float*)d_in[13];
    const float* w_mu  = (const float*)d_in[14], *b_mu  = (const float*)d_in[15];
    const float* w_lv  = (const float*)d_in[16], *b_lv  = (const float*)d_in[17];
    const float* w_dec = (const float*)d_in[18], *b_dec = (const float*)d_in[19];
    const float* veps  = (const float*)d_in[20];
    const float* w1 = (const float*)d_in[21], *a_src1 = (const float*)d_in[22];
    const float* a_dst1 = (const float*)d_in[23], *b1 = (const float*)d_in[24];
    const float* w2 = (const float*)d_in[25], *a_src2 = (const float*)d_in[26];
    const float* a_dst2 = (const float*)d_in[27], *b2 = (const float*)d_in[28];
    float* out = (float*)d_out;

    float *GI0, *GI1, *OUT0, *GH, *h0b, *h1b, *mu, *lv, *z, *rec, *xin;
    float *xp1, *as1, *ad1, *e1, *emax1, *den1, *agg1;
    float *xp2, *as2, *ad2, *e2, *emax2, *den2, *acc;
    int* tok;
    cudaGetSymbolAddress((void**)&GI0, g_GI0);
    cudaGetSymbolAddress((void**)&GI1, g_GI1);
    cudaGetSymbolAddress((void**)&OUT0, g_OUT0);
    cudaGetSymbolAddress((void**)&GH, g_GH);
    cudaGetSymbolAddress((void**)&h0b, g_h0);
    cudaGetSymbolAddress((void**)&h1b, g_h1);
    cudaGetSymbolAddress((void**)&tok, g_tok);
    cudaGetSymbolAddress((void**)&mu, g_mu);
    cudaGetSymbolAddress((void**)&lv, g_lv);
    cudaGetSymbolAddress((void**)&z, g_zbuf);
    cudaGetSymbolAddress((void**)&rec, g_rec);
    cudaGetSymbolAddress((void**)&xin, g_xin);
    cudaGetSymbolAddress((void**)&xp1, g_xp1);
    cudaGetSymbolAddress((void**)&as1, g_as1);
    cudaGetSymbolAddress((void**)&ad1, g_ad1);
    cudaGetSymbolAddress((void**)&e1, g_e1);
    cudaGetSymbolAddress((void**)&emax1, g_emax1);
    cudaGetSymbolAddress((void**)&den1, g_den1);
    cudaGetSymbolAddress((void**)&agg1, g_agg1);
    cudaGetSymbolAddress((void**)&xp2, g_xp2);
    cudaGetSymbolAddress((void**)&as2, g_as2);
    cudaGetSymbolAddress((void**)&ad2, g_ad2);
    cudaGetSymbolAddress((void**)&e2, g_e2);
    cudaGetSymbolAddress((void**)&emax2, g_emax2);
    cudaGetSymbolAddress((void**)&den2, g_den2);
    cudaGetSymbolAddress((void**)&acc, g_acc);

    // opt-in to 80KB dynamic smem for the tensor-core GEMM (attribute, not allocation)
    cudaFuncSetAttribute((const void*)gemm_k<true, true>,
                         cudaFuncAttributeMaxDynamicSharedMemorySize, GSMEM_BYTES);
    cudaFuncSetAttribute((const void*)gemm_k<true, false>,
                         cudaFuncAttributeMaxDynamicSharedMemorySize, GSMEM_BYTES);
    cudaFuncSetAttribute((const void*)gemm_k<false, false>,
                         cudaFuncAttributeMaxDynamicSharedMemorySize, GSMEM_BYTES);

    const dim3 blk(512);

    // ---- per-launch init (determinism) ----
    init_all_k<<<cd(INIT_TOTAL, 256), 256>>>(emax1, den1, agg1, emax2, den2, out, acc);
    copy_k<<<cd(NTV * HH, 256), 256>>>(h0b, h0, NTV * HH);
    copy_k<<<cd(NTV * HH, 256), 256>>>(h1b, h0 + NTV * HH, NTV * HH);
    tok_k<<<cd(MM0, 256), 256>>>(tok, gnf);

    // ---- GRU layer 0: batched input projection (gather fused) ----
    {
        dim3 g(cd(GG, 128), cd(MM0, 128));
        gemm_k<true, true><<<g, blk, GSMEM_BYTES>>>(emb, w_ih0, b_ih0, GI0, MM0, GG, DD, tok);
    }
    for (int t = 0; t < TT; t++) {
        dim3 g(cd(GG, 128), cd(NTV, 128));
        gemm_k<true, false><<<g, blk, GSMEM_BYTES>>>(h0b, w_hh0, b_hh0, GH, NTV, GG, HH, nullptr);
        gru_gate_k<<<cd(NTV * HH, 256), 256>>>(GI0 + (size_t)t * NTV * GG, GH, h0b,
                                               OUT0 + (size_t)t * NTV * HH);
    }
    // ---- GRU layer 1: batched input projection from OUT0 ----
    {
        dim3 g(cd(GG, 128), cd(MM0, 128));
        gemm_k<true, false><<<g, blk, GSMEM_BYTES>>>(OUT0, w_ih1, b_ih1, GI1, MM0, GG, HH, nullptr);
    }
    for (int t = 0; t < TT; t++) {
        dim3 g(cd(GG, 128), cd(NTV, 128));
        gemm_k<true, false><<<g, blk, GSMEM_BYTES>>>(h1b, w_hh1, b_hh1, GH, NTV, GG, HH, nullptr);
        gru_gate_k<<<cd(NTV * HH, 256), 256>>>(GI1 + (size_t)t * NTV * GG, GH, h1b, nullptr);
    }

    // ---- VAE ----
    {
        dim3 g(cd(ZZ, 128), cd(NUV, 128));
        gemm_k<true, false><<<g, blk, GSMEM_BYTES>>>(user_feats, w_mu, b_mu, mu, NUV, ZZ, FF, nullptr);
        gemm_k<true, false><<<g, blk, GSMEM_BYTES>>>(user_feats, w_lv, b_lv, lv, NUV, ZZ, FF, nullptr);
    }
    vae_z_kl_k<<<cd(NUV * ZZ, 256), 256>>>(mu, lv, veps, z, acc);
    {
        dim3 g(cd(FF, 128), cd(NUV, 128));
        gemm_k<true, false><<<g, blk, GSMEM_BYTES>>>(z, w_dec, b_dec, rec, NUV, FF, ZZ, nullptr);
    }
    rec_loss_k<<<cd(NUV * FF, 256), 256>>>(rec, user_feats, acc);

    // ---- node feature assembly ----
    assemble_k<<<cd(NN * HH, 256), 256>>>(h1b, z, xin);

    // ---- GAT layer 1 (8 heads x 64, concat) ----
    {
        dim3 g(cd(NHEADS * CC1, 128), cd(NN, 128));
        gemm_k<false, false><<<g, blk, GSMEM_BYTES>>>(xin, w1, nullptr, xp1, NN, NHEADS * CC1, HH, nullptr);
    }
    asad_k<<<cd(NN * NHEADS, 256), 256>>>(xp1, a_src1, a_dst1, as1, ad1, NHEADS, CC1);
    edgeA_k<<<cd((long)ETOT * NHEADS, 256), 256>>>(as1, ad1, ei, e1, emax1, NHEADS);
    edgeB_k<<<cd((long)ETOT * NHEADS, 256), 256>>>(ei, e1, emax1, den1, NHEADS);
    edgeC_k<<<cd((long)ETOT * NHEADS * CC1 / 4, 256), 256>>>(xp1, e1, den1, ei, agg1, NHEADS, CC1);
    addbias_k<<<cd(NN * NHEADS * CC1, 256), 256>>>(agg1, b1, NHEADS * CC1, NN * NHEADS * CC1);

    // ---- GAT layer 2 (1 head x 100, mean == identity) ----
    {
        dim3 g(cd(CC2, 128), cd(NN, 128));
        gemm_k<false, false><<<g, blk, GSMEM_BYTES>>>(agg1, w2, nullptr, xp2, NN, CC2, NHEADS * CC1, nullptr);
    }
    asad_k<<<cd(NN, 256), 256>>>(xp2, a_src2, a_dst2, as2, ad2, 1, CC2);
    edgeA_k<<<cd(ETOT, 256), 256>>>(as2, ad2, ei, e2, emax2, 1);
    edgeB_k<<<cd(ETOT, 256), 256>>>(ei, e2, emax2, den2, 1);
    edgeC_k<<<cd((long)ETOT * CC2 / 4, 256), 256>>>(xp2, e2, den2, ei, out, 1, CC2);
    addbias_k<<<cd(NN * CC2, 256), 256>>>(out, b2, CC2, NN * CC2);

    // ---- scalar losses ----
    scalars_k<<<1, 32>>>(acc, out, out_size);
}

// round 10
// speedup vs baseline: 2.9962x; 1.1592x over previous
#include <cuda_runtime.h>
#include <cuda_bf16.h>
#include <cstddef>

// ---------------- problem dims ----------------
#define TT 24          // seq len
#define DD 300         // glove dim
#define HH 256         // GRU hidden / z dim
#define NTV 6000       // tweet nodes
#define NUV 4000       // user nodes
#define NN 10000       // total nodes
#define FF 512         // user feat size
#define ZZ 256         // z dim
#define EE 80000       // edges
#define BB 2000        // batch (source tweets)
#define CC1 64         // GAT1 out channels
#define CC2 100        // GAT2 out channels
#define NHEADS 8
#define GG 768         // 3*H
#define MM0 (TT*NTV)   // 144000
#define ETOT (EE+NN)   // 90000 (edges + self loops)

// ---------------- scratch (device globals; no allocation allowed) ----------------
__device__ float g_GI0[(size_t)MM0*GG];
__device__ float g_GI1[(size_t)MM0*GG];
__device__ float g_OUT0[(size_t)MM0*HH];
__device__ float g_GH0[NTV*GG];
__device__ float g_GH1[NTV*GG];
__device__ float g_h0[NTV*HH];
__device__ float g_h1[NTV*HH];
__device__ int   g_tok[MM0];
__device__ float g_mu[NUV*ZZ];
__device__ float g_lv[NUV*ZZ];
__device__ float g_zbuf[NUV*ZZ];
__device__ float g_rec[NUV*FF];
__device__ float g_xin[NN*HH];
__device__ float g_xp1[NN*NHEADS*CC1];
__device__ float g_as1[NN*NHEADS];
__device__ float g_ad1[NN*NHEADS];
__device__ float g_e1[ETOT*NHEADS];
__device__ float g_emax1[NN*NHEADS];
__device__ float g_den1[NN*NHEADS];
__device__ float g_agg1[NN*NHEADS*CC1];
__device__ float g_xp2[NN*CC2];
__device__ float g_as2[NN];
__device__ float g_ad2[NN];
__device__ float g_e2[ETOT];
__device__ float g_emax2[NN];
__device__ float g_den2[NN];
__device__ float g_acc[2];

// ---------------- small helpers ----------------
__device__ __forceinline__ float sigmoidf_(float x) { return 1.f / (1.f + expf(-x)); }

__device__ __forceinline__ void atomicMaxFloat(float* addr, float val) {
    int old = __float_as_int(*addr);
    while (__int_as_float(old) < val) {
        int assumed = old;
        old = atomicCAS((int*)addr, assumed, __float_as_int(val));
        if (old == assumed) break;
    }
}

__device__ __forceinline__ void redAdd4(float* addr, float a, float b, float c, float d) {
    asm volatile("red.global.add.v4.f32 [%0], {%1, %2, %3, %4};"
                 :: "l"(addr), "f"(a), "f"(b), "f"(c), "f"(d) : "memory");
}

__device__ __forceinline__ void block_reduce_add(float v, float* target) {
    #pragma unroll
    for (int o = 16; o > 0; o >>= 1) v += __shfl_down_sync(0xffffffffu, v, o);
    __shared__ float s[16];
    int lane = threadIdx.x & 31, w = threadIdx.x >> 5;
    if (lane == 0) s[w] = v;
    __syncthreads();
    if (w == 0) {
        v = (lane < (int)(blockDim.x >> 5)) ? s[lane] : 0.f;
        #pragma unroll
        for (int o = 8; o > 0; o >>= 1) v += __shfl_down_sync(0xffffffffu, v, o);
        if (lane == 0) atomicAdd(target, v);
    }
}

// ================= GEMM: bf16 3-term split on tensor cores =================
// C = A @ op(B) (+bias), fp32 in/out, internally a_hi*b_hi + a_hi*b_lo + a_lo*b_hi
// BT=true : B is (N,K) row-major -> C = A @ B^T
// BT=false: B is (K,N) row-major -> C = A @ B
// GATHER  : A row m is A[rowidx[m]]
// Block: 512 threads (16 warps, 4x4 grid, 32x32 warp tile), tile 128x128x32.
#define LDB 40                       // bf16 elems per smem row (32 + 8 pad)
#define LDC 136                      // fp32 stride for epilogue staging
#define GTILE (128*LDB)              // elems per smem sub-tile
#define GSMEM_BYTES (8*GTILE*2)      // 81920 B (2 bufs x {Ahi,Alo,Bhi,Blo})

__device__ __forceinline__ void ldmx4(unsigned* d, const unsigned short* p) {
    unsigned addr = (unsigned)__cvta_generic_to_shared(p);
    asm volatile("ldmatrix.sync.aligned.m8n8.x4.shared.b16 {%0,%1,%2,%3}, [%4];"
        : "=r"(d[0]), "=r"(d[1]), "=r"(d[2]), "=r"(d[3]) : "r"(addr));
}
__device__ __forceinline__ void mma_bf16(float* d, const unsigned* a, unsigned b0, unsigned b1) {
    asm volatile("mma.sync.aligned.m16n8k16.row.col.f32.bf16.bf16.f32 "
        "{%0,%1,%2,%3}, {%4,%5,%6,%7}, {%8,%9}, {%0,%1,%2,%3};"
        : "+f"(d[0]), "+f"(d[1]), "+f"(d[2]), "+f"(d[3])
        : "r"(a[0]), "r"(a[1]), "r"(a[2]), "r"(a[3]), "r"(b0), "r"(b1));
}
__device__ __forceinline__ void cvt_store8(unsigned short* hi, unsigned short* lo,
                                           int off, float4 v) {
    ushort4 h, l;
    __nv_bfloat16 b;
    b = __float2bfloat16(v.x); h.x = __bfloat16_as_ushort(b);
    l.x = __bfloat16_as_ushort(__float2bfloat16(v.x - __bfloat162float(b)));
    b = __float2bfloat16(v.y); h.y = __bfloat16_as_ushort(b);
    l.y = __bfloat16_as_ushort(__float2bfloat16(v.y - __bfloat162float(b)));
    b = __float2bfloat16(v.z); h.z = __bfloat16_as_ushort(b);
    l.z = __bfloat16_as_ushort(__float2bfloat16(v.z - __bfloat162float(b)));
    b = __float2bfloat16(v.w); h.w = __bfloat16_as_ushort(b);
    l.w = __bfloat16_as_ushort(__float2bfloat16(v.w - __bfloat162float(b)));
    *(ushort4*)(hi + off) = h;
    *(ushort4*)(lo + off) = l;
}

template<bool BT, bool GATHER>
__global__ __launch_bounds__(512, 1)
void gemm_k(const float* __restrict__ A, const float* __restrict__ Bm,
            const float* __restrict__ bias, float* __restrict__ Cc,
            int M, int Nc, int K, const int* __restrict__ rowidx)
{
    extern __shared__ unsigned short SMEM[];
    __shared__ int ridx[128];

    const int tid = threadIdx.x;
    const int lane = tid & 31, wid = tid >> 5;
    const int wm = wid & 3, wn = wid >> 2;   // 4x4 warps, each 32x32
    const int bm = blockIdx.y * 128, bn = blockIdx.x * 128;

    if (tid < 128) {
        int r = bm + tid;
        ridx[tid] = (r < M) ? (GATHER ? rowidx[r] : r) : -1;
    }
    __syncthreads();

    float acc[2][4][4];
    #pragma unroll
    for (int i = 0; i < 2; i++)
        #pragma unroll
        for (int j = 0; j < 4; j++)
            #pragma unroll
            for (int q = 0; q < 4; q++) acc[i][j][q] = 0.f;

    // loader coords
    const int a_r = tid >> 3;          // 0..63 (+64 for second chunk)
    const int a_k = (tid & 7) << 2;    // 0,4,...,28
    const int b_n = tid & 127;         // non-BT: n within tile
    const int b_k = (tid >> 7) << 2;   // 0,4,8,12 (+16 for second chunk)

    float4 fa0, fa1, fb0, fb1;

    auto FETCH = [&](int kt) {
        const float4 z4 = make_float4(0.f, 0.f, 0.f, 0.f);
        int gr = ridx[a_r];
        fa0 = (gr >= 0 && kt + a_k < K) ? *(const float4*)(A + (size_t)gr * K + kt + a_k) : z4;
        gr = ridx[a_r + 64];
        fa1 = (gr >= 0 && kt + a_k < K) ? *(const float4*)(A + (size_t)gr * K + kt + a_k) : z4;
        if (BT) {
            int n = bn + a_r;
            fb0 = (n < Nc && kt + a_k < K) ? *(const float4*)(Bm + (size_t)n * K + kt + a_k) : z4;
            n = bn + a_r + 64;
            fb1 = (n < Nc && kt + a_k < K) ? *(const float4*)(Bm + (size_t)n * K + kt + a_k) : z4;
        } else {
            bool nok = (bn + b_n) < Nc;
            float t0[4], t1[4];
            #pragma unroll
            for (int i = 0; i < 4; i++) {
                int k0 = kt + b_k + i, k1 = kt + b_k + 16 + i;
                t0[i] = (nok && k0 < K) ? Bm[(size_t)k0 * Nc + bn + b_n] : 0.f;
                t1[i] = (nok && k1 < K) ? Bm[(size_t)k1 * Nc + bn + b_n] : 0.f;
            }
            fb0 = make_float4(t0[0], t0[1], t0[2], t0[3]);
            fb1 = make_float4(t1[0], t1[1], t1[2], t1[3]);
        }
    };
    auto STORE = [&](int buf) {
        unsigned short* Ah = SMEM + (buf * 4 + 0) * GTILE;
        unsigned short* Al = SMEM + (buf * 4 + 1) * GTILE;
        unsigned short* Bh = SMEM + (buf * 4 + 2) * GTILE;
        unsigned short* Bl = SMEM + (buf * 4 + 3) * GTILE;
        cvt_store8(Ah, Al, a_r * LDB + a_k, fa0);
        cvt_store8(Ah, Al, (a_r + 64) * LDB + a_k, fa1);
        if (BT) {
            cvt_store8(Bh, Bl, a_r * LDB + a_k, fb0);
            cvt_store8(Bh, Bl, (a_r + 64) * LDB + a_k, fb1);
        } else {
            cvt_store8(Bh, Bl, b_n * LDB + b_k, fb0);
            cvt_store8(Bh, Bl, b_n * LDB + b_k + 16, fb1);
        }
    };

    const int nT = (K + 31) >> 5;
    FETCH(0); STORE(0); __syncthreads();

    const int lr = lane & 15, lko = (lane >> 4) << 3;

    for (int t = 0; t < nT; t++) {
        const int buf = t & 1;
        if (t + 1 < nT) FETCH((t + 1) << 5);
        const unsigned short* Ah = SMEM + (buf * 4 + 0) * GTILE;
        const unsigned short* Al = SMEM + (buf * 4 + 1) * GTILE;
        const unsigned short* Bh = SMEM + (buf * 4 + 2) * GTILE;
        const unsigned short* Bl = SMEM + (buf * 4 + 3) * GTILE;
        #pragma unroll
        for (int kc = 0; kc < 32; kc += 16) {
            unsigned ah[2][4], al[2][4];
            #pragma unroll
            for (int mf = 0; mf < 2; mf++) {
                int off = (wm * 32 + mf * 16 + lr) * LDB + kc + lko;
                ldmx4(ah[mf], Ah + off);
                ldmx4(al[mf], Al + off);
            }
            #pragma unroll
            for (int np = 0; np < 2; np++) {
                int off = (wn * 32 + np * 16 + lr) * LDB + kc + lko;
                unsigned bh[4], bl[4];
                ldmx4(bh, Bh + off);
                ldmx4(bl, Bl + off);
                #pragma unroll
                for (int mf = 0; mf < 2; mf++)
                    #pragma unroll
                    for (int s = 0; s < 2; s++) {
                        float* d = acc[mf][np * 2 + s];
                        mma_bf16(d, ah[mf], bh[s], bh[s + 2]);  // hi*hi
                        mma_bf16(d, ah[mf], bl[s], bl[s + 2]);  // hi*lo
                        mma_bf16(d, al[mf], bh[s], bh[s + 2]);  // lo*hi
                    }
            }
        }
        if (t + 1 < nT) STORE(buf ^ 1);
        __syncthreads();
    }

    // ---- epilogue: stage C through smem for coalesced gmem stores ----
    float* Cs = (float*)SMEM;
    #pragma unroll
    for (int mf = 0; mf < 2; mf++)
        #pragma unroll
        for (int nf = 0; nf < 4; nf++) {
            int r = wm * 32 + mf * 16 + (lane >> 2);
            int c = wn * 32 + nf * 8 + (lane & 3) * 2;
            *(float2*)&Cs[r * LDC + c]       = make_float2(acc[mf][nf][0], acc[mf][nf][1]);
            *(float2*)&Cs[(r + 8) * LDC + c] = make_float2(acc[mf][nf][2], acc[mf][nf][3]);
        }
    __syncthreads();
    #pragma unroll
    for (int q = 0; q < 8; q++) {
        int idx = q * 512 + tid;
        int row = idx >> 5, c4 = (idx & 31) << 2;
        int grow = bm + row, gcol = bn + c4;
        if (grow < M && gcol < Nc) {
            float4 v = *(float4*)&Cs[row * LDC + c4];
            if (bias) {
                v.x += bias[gcol];     v.y += bias[gcol + 1];
                v.z += bias[gcol + 2]; v.w += bias[gcol + 3];
            }
            *(float4*)(Cc + (size_t)grow * Nc + gcol) = v;
        }
    }
}

// ---------------- fused init ----------------
#define INIT_E1 (NN*NHEADS)
#define INIT_D1 (NN*NHEADS)
#define INIT_AG (NN*NHEADS*CC1)
#define INIT_O  (NN*CC2)
#define INIT_TOTAL (INIT_E1 + INIT_D1 + INIT_AG + NN + NN + INIT_O + 2)
__global__ void init_all_k(float* emax1, float* den1, float* agg1,
                           float* emax2, float* den2, float* out, float* acc) {
    int i = blockIdx.x * blockDim.x + threadIdx.x;
    if (i >= INIT_TOTAL) return;
    if (i < INIT_E1) { emax1[i] = -1e30f; return; }
    i -= INIT_E1;
    if (i < INIT_D1) { den1[i] = 0.f; return; }
    i -= INIT_D1;
    if (i < INIT_AG) { agg1[i] = 0.f; return; }
    i -= INIT_AG;
    if (i < NN) { emax2[i] = -1e30f; return; }
    i -= NN;
    if (i < NN) { den2[i] = 0.f; return; }
    i -= NN;
    if (i < INIT_O) { out[i] = 0.f; return; }
    i -= INIT_O;
    acc[i] = 0.f;
}

// ---------------- elementwise / utility kernels ----------------
__global__ void copy_k(float* dst, const float* src, int n) {
    int i = blockIdx.x * blockDim.x + threadIdx.x;
    if (i < n) dst[i] = src[i];
}
__global__ void tok_k(int* tok, const int* gnf) {
    int i = blockIdx.x * blockDim.x + threadIdx.x;
    if (i >= MM0) return;
    int t = i / NTV, n = i % NTV;
    tok[i] = gnf[n * TT + t];
}
// torch GRU gate math, float4-vectorized; in-place h update, optional out copy
__global__ void gru_gate_k(const float* __restrict__ GI, const float* __restrict__ GH,
                           float* __restrict__ h, float* __restrict__ o) {
    int idx = blockIdx.x * blockDim.x + threadIdx.x;   // over NTV * (HH/4)
    if (idx >= NTV * (HH / 4)) return;
    int n = idx >> 6, j4 = (idx & 63) << 2;
    const float* gi = GI + (size_t)n * GG;
    const float* gh = GH + (size_t)n * GG;
    float4 gir = *(const float4*)(gi + j4);
    float4 giz = *(const float4*)(gi + HH + j4);
    float4 gin = *(const float4*)(gi + 2 * HH + j4);
    float4 ghr = *(const float4*)(gh + j4);
    float4 ghz = *(const float4*)(gh + HH + j4);
    float4 ghn = *(const float4*)(gh + 2 * HH + j4);
    float4 hv = *(const float4*)(h + (size_t)n * HH + j4);
    float4 hn;
    #define GATE1(c) { \
        float r = sigmoidf_(gir.c + ghr.c); \
        float z = sigmoidf_(giz.c + ghz.c); \
        float nn_ = tanhf(gin.c + r * ghn.c); \
        hn.c = (1.f - z) * nn_ + z * hv.c; }
    GATE1(x) GATE1(y) GATE1(z) GATE1(w)
    #undef GATE1
    *(float4*)(h + (size_t)n * HH + j4) = hn;
    if (o) *(float4*)(o + (size_t)n * HH + j4) = hn;
}
__global__ void vae_z_kl_k(const float* mu, const float* lv, const float* eps,
                           float* z, float* acc) {
    int i = blockIdx.x * blockDim.x + threadIdx.x;
    float term = 0.f;
    if (i < NUV * ZZ) {
        float m = mu[i], l = lv[i];
        z[i] = m + expf(0.5f * l) * eps[i];
        term = 1.f + l - m * m - expf(l);
    }
    block_reduce_add(term, &acc[0]);
}
__global__ void rec_loss_k(const float* rec, const float* uf, float* acc) {
    int i = blockIdx.x * blockDim.x + threadIdx.x;
    float term = 0.f;
    if (i < NUV * FF) {
        float d = rec[i] - uf[i];
        term = d * d;
    }
    block_reduce_add(term, &acc[1]);
}
__global__ void assemble_k(const float* hn, const float* z, float* xin) {
    int i = blockIdx.x * blockDim.x + threadIdx.x;
    if (i >= NN * HH) return;
    int row = i >> 8, j = i & 255;
    float v;
    if (row < BB)            v = hn[row * HH + j];
    else if (row < BB + NUV) v = z[(row - BB) * ZZ + j];
    else                     v = hn[(row - NUV) * HH + j];
    xin[i] = v;
}
__global__ void asad_k(const float* __restrict__ xp, const float* __restrict__ a_src,
                       const float* __restrict__ a_dst, float* as_n, float* ad_n,
                       int heads, int C) {
    int idx = blockIdx.x * blockDim.x + threadIdx.x;
    if (idx >= NN * heads) return;
    int node = idx / heads, h = idx % heads;
    const float* row = xp + (long)node * heads * C + h * C;
    float s = 0.f, d = 0.f;
    for (int c = 0; c < C; c++) { float v = row[c]; s += v * a_src[h * C + c]; d += v * a_dst[h * C + c]; }
    as_n[idx] = s; ad_n[idx] = d;
}
__device__ __forceinline__ void edge_sd(int e, const int* ei, int& s, int& d) {
    if (e < EE) { s = ei[e]; d = ei[EE + e]; } else { s = d = e - EE; }
}
__global__ void edgeA_k(const float* as_n, const float* ad_n, const int* ei,
                        float* ebuf, float* emax, int heads) {
    int idx = blockIdx.x * blockDim.x + threadIdx.x;
    if (idx >= ETOT * heads) return;
    int e = idx / heads, h = idx % heads;
    int s, d; edge_sd(e, ei, s, d);
    float v = as_n[s * heads + h] + ad_n[d * heads + h];
    v = v > 0.f ? v : 0.2f * v;
    ebuf[idx] = v;
    atomicMaxFloat(&emax[d * heads + h], v);
}
__global__ void edgeB_k(const int* ei, float* ebuf, const float* emax,
                        float* den, int heads) {
    int idx = blockIdx.x * blockDim.x + threadIdx.x;
    if (idx >= ETOT * heads) return;
    int e = idx / heads, h = idx % heads;
    int s, d; edge_sd(e, ei, s, d);
    float ee = expf(ebuf[idx] - emax[d * heads + h]);
    ebuf[idx] = ee;
    atomicAdd(&den[d * heads + h], ee);
}
__global__ void edgeC_k(const float* __restrict__ xp, const float* __restrict__ ebuf,
                        const float* __restrict__ den, const int* __restrict__ ei,
                        float* __restrict__ agg, int heads, int C) {
    int Q = heads * C / 4;
    long idx = (long)blockIdx.x * blockDim.x + threadIdx.x;
    if (idx >= (long)ETOT * Q) return;
    int e = (int)(idx / Q), q = (int)(idx % Q);
    int c0 = q * 4, h = c0 / C;
    int s, d; edge_sd(e, ei, s, d);
    float al = ebuf[e * heads + h] / den[d * heads + h];
    const float4 v = *(const float4*)(xp + (long)s * heads * C + c0);
    float* dst = agg + (long)d * heads * C + c0;
    redAdd4(dst, v.x * al, v.y * al, v.z * al, v.w * al);
}
__global__ void addbias_k(float* x, const float* b, int cols, int total) {
    int i = blockIdx.x * blockDim.x + threadIdx.x;
    if (i < total) x[i] += b[i % cols];
}
__global__ void scalars_k(const float* acc, float* out, int os) {
    if (threadIdx.x == 0) {
        out[os - 2] = -0.5f * acc[0] / (float)NUV;
        out[os - 1] = acc[1] / ((float)NUV * (float)FF);
    }
}

// ---------------- host orchestration ----------------
static inline int cd(long a, long b) { return (int)((a + b - 1) / b); }

extern "C" void kernel_launch(void* const* d_in, const int* in_sizes, int n_in,
                              void* d_out, int out_size) {
    (void)in_sizes; (void)n_in;
    const float* user_feats = (const float*)d_in[1];
    const int*   gnf  = (const int*)d_in[2];
    const int*   ei   = (const int*)d_in[3];
    const float* emb  = (const float*)d_in[4];
    const float* w_ih0 = (const float*)d_in[5],  *w_hh0 = (const float*)d_in[6];
    const float* b_ih0 = (const float*)d_in[7],  *b_hh0 = (const float*)d_in[8];
    const float* w_ih1 = (const float*)d_in[9],  *w_hh1 = (const float*)d_in[10];
    const float* b_ih1 = (const float*)d_in[11], *b_hh1 = (const float*)d_in[12];
    const float* h0    = (const float*)d_in[13];
    const float* w_mu  = (const float*)d_in[14], *b_mu  = (const float*)d_in[15];
    const float* w_lv  = (const float*)d_in[16], *b_lv  = (const float*)d_in[17];
    const float* w_dec = (const float*)d_in[18], *b_dec = (const float*)d_in[19];
    const float* veps  = (const float*)d_in[20];
    const float* w1 = (const float*)d_in[21], *a_src1 = (const float*)d_in[22];
    const float* a_dst1 = (const float*)d_in[23], *b1 = (const float*)d_in[24];
    const float* w2 = (const float*)d_in[25], *a_src2 = (const float*)d_in[26];
    const float* a_dst2 = (const float*)d_in[27], *b2 = (const float*)d_in[28];
    float* out = (float*)d_out;

    float *GI0, *GI1, *OUT0, *GH0, *GH1, *h0b, *h1b, *mu, *lv, *z, *rec, *xin;
    float *xp1, *as1, *ad1, *e1, *emax1, *den1, *agg1;
    float *xp2, *as2, *ad2, *e2, *emax2, *den2, *acc;
    int* tok;
    cudaGetSymbolAddress((void**)&GI0, g_GI0);
    cudaGetSymbolAddress((void**)&GI1, g_GI1);
    cudaGetSymbolAddress((void**)&OUT0, g_OUT0);
    cudaGetSymbolAddress((void**)&GH0, g_GH0);
    cudaGetSymbolAddress((void**)&GH1, g_GH1);
    cudaGetSymbolAddress((void**)&h0b, g_h0);
    cudaGetSymbolAddress((void**)&h1b, g_h1);
    cudaGetSymbolAddress((void**)&tok, g_tok);
    cudaGetSymbolAddress((void**)&mu, g_mu);
    cudaGetSymbolAddress((void**)&lv, g_lv);
    cudaGetSymbolAddress((void**)&z, g_zbuf);
    cudaGetSymbolAddress((void**)&rec, g_rec);
    cudaGetSymbolAddress((void**)&xin, g_xin);
    cudaGetSymbolAddress((void**)&xp1, g_xp1);
    cudaGetSymbolAddress((void**)&as1, g_as1);
    cudaGetSymbolAddress((void**)&ad1, g_ad1);
    cudaGetSymbolAddress((void**)&e1, g_e1);
    cudaGetSymbolAddress((void**)&emax1, g_emax1);
    cudaGetSymbolAddress((void**)&den1, g_den1);
    cudaGetSymbolAddress((void**)&agg1, g_agg1);
    cudaGetSymbolAddress((void**)&xp2, g_xp2);
    cudaGetSymbolAddress((void**)&as2, g_as2);
    cudaGetSymbolAddress((void**)&ad2, g_ad2);
    cudaGetSymbolAddress((void**)&e2, g_e2);
    cudaGetSymbolAddress((void**)&emax2, g_emax2);
    cudaGetSymbolAddress((void**)&den2, g_den2);
    cudaGetSymbolAddress((void**)&acc, g_acc);

    // ---- streams/events: created ONCE on the first call (the correctness
    // run), so nothing is allocated during graph capture and the post-teardown
    // memory checkpoint returns to its pre-capture baseline. Every call issues
    // the identical launch sequence (deterministic work).
    static bool s_init = false;
    static cudaStream_t sB, sC, sD;
    static cudaEvent_t evStart, evB, ev0[TT], evC[TT], evD[TT];
    if (!s_init) {
        cudaStreamCreateWithFlags(&sB, cudaStreamNonBlocking);
        cudaStreamCreateWithFlags(&sC, cudaStreamNonBlocking);
        cudaStreamCreateWithFlags(&sD, cudaStreamNonBlocking);
        cudaEventCreateWithFlags(&evStart, cudaEventDisableTiming);
        cudaEventCreateWithFlags(&evB, cudaEventDisableTiming);
        for (int t = 0; t < TT; t++) {
            cudaEventCreateWithFlags(&ev0[t], cudaEventDisableTiming);
            cudaEventCreateWithFlags(&evC[t], cudaEventDisableTiming);
            cudaEventCreateWithFlags(&evD[t], cudaEventDisableTiming);
        }
        cudaFuncSetAttribute((const void*)gemm_k<true, true>,
                             cudaFuncAttributeMaxDynamicSharedMemorySize, GSMEM_BYTES);
        cudaFuncSetAttribute((const void*)gemm_k<true, false>,
                             cudaFuncAttributeMaxDynamicSharedMemorySize, GSMEM_BYTES);
        cudaFuncSetAttribute((const void*)gemm_k<false, false>,
                             cudaFuncAttributeMaxDynamicSharedMemorySize, GSMEM_BYTES);
        s_init = true;
    }
    cudaStream_t s0 = 0;

    const dim3 blk(512);
    const dim3 gR(cd(GG, 128), cd(NTV, 128));    // per-step GEMM grid
    const int  gGate = cd(NTV * (HH / 4), 256);

    // ---- s0: init ----
    init_all_k<<<cd(INIT_TOTAL, 256), 256, 0, s0>>>(emax1, den1, agg1, emax2, den2, out, acc);
    copy_k<<<cd(NTV * HH, 256), 256, 0, s0>>>(h0b, h0, NTV * HH);
    copy_k<<<cd(NTV * HH, 256), 256, 0, s0>>>(h1b, h0 + NTV * HH, NTV * HH);
    tok_k<<<cd(MM0, 256), 256, 0, s0>>>(tok, gnf);
    cudaEventRecord(evStart, s0);

    // ---- sB: VAE (independent of GRU; runs under the early recurrent steps) ----
    cudaStreamWaitEvent(sB, evStart, 0);
    {
        dim3 g(cd(ZZ, 128), cd(NUV, 128));
        gemm_k<true, false><<<g, blk, GSMEM_BYTES, sB>>>(user_feats, w_mu, b_mu, mu, NUV, ZZ, FF, nullptr);
        gemm_k<true, false><<<g, blk, GSMEM_BYTES, sB>>>(user_feats, w_lv, b_lv, lv, NUV, ZZ, FF, nullptr);
    }
    vae_z_kl_k<<<cd(NUV * ZZ, 256), 256, 0, sB>>>(mu, lv, veps, z, acc);
    {
        dim3 g(cd(FF, 128), cd(NUV, 128));
        gemm_k<true, false><<<g, blk, GSMEM_BYTES, sB>>>(z, w_dec, b_dec, rec, NUV, FF, ZZ, nullptr);
    }
    rec_loss_k<<<cd(NUV * FF, 256), 256, 0, sB>>>(rec, user_feats, acc);

    // ---- sD: GI0 in per-step chunks (gather fused); recurrence starts as soon
    //      as chunk 0 lands instead of after the whole 66 GF projection ----
    cudaStreamWaitEvent(sD, evStart, 0);
    for (int t = 0; t < TT; t++) {
        gemm_k<true, true><<<gR, blk, GSMEM_BYTES, sD>>>(emb, w_ih0, b_ih0,
                                                         GI0 + (size_t)t * NTV * GG,
                                                         NTV, GG, DD, tok + (size_t)t * NTV);
        cudaEventRecord(evD[t], sD);
    }

    // ---- pipelined GRU recurrence ----
    // s0: layer-0 chain; sC: per-step GI1 chunk (dep gate0(t)); sB: layer-1 chain.
    cudaStreamWaitEvent(sC, evStart, 0);
    for (int t = 0; t < TT; t++) {
        // layer 0, step t (s0): hh-GEMM doesn't need GI0; gate does (chunk t)
        gemm_k<true, false><<<gR, blk, GSMEM_BYTES, s0>>>(h0b, w_hh0, b_hh0, GH0, NTV, GG, HH, nullptr);
        cudaStreamWaitEvent(s0, evD[t], 0);
        gru_gate_k<<<gGate, 256, 0, s0>>>(GI0 + (size_t)t * NTV * GG, GH0, h0b,
                                          OUT0 + (size_t)t * NTV * HH);
        cudaEventRecord(ev0[t], s0);

        // GI1 chunk for step t (sC) - needs OUT0[t]
        cudaStreamWaitEvent(sC, ev0[t], 0);
        gemm_k<true, false><<<gR, blk, GSMEM_BYTES, sC>>>(OUT0 + (size_t)t * NTV * HH, w_ih1, b_ih1,
                                                          GI1 + (size_t)t * NTV * GG, NTV, GG, HH, nullptr);
        cudaEventRecord(evC[t], sC);

        // layer 1, step t (sB) - needs GI1 chunk t and h1b from step t-1 (sB-serial)
        cudaStreamWaitEvent(sB, evC[t], 0);
        gemm_k<true, false><<<gR, blk, GSMEM_BYTES, sB>>>(h1b, w_hh1, b_hh1, GH1, NTV, GG, HH, nullptr);
        gru_gate_k<<<gGate, 256, 0, sB>>>(GI1 + (size_t)t * NTV * GG, GH1, h1b, nullptr);
    }
    cudaEventRecord(evB, sB);
    cudaStreamWaitEvent(s0, evB, 0);   // join: h1b, z, acc all ready

    // ---- node feature assembly ----
    assemble_k<<<cd(NN * HH, 256), 256, 0, s0>>>(h1b, z, xin);

    // ---- GAT layer 1 (8 heads x 64, concat) ----
    {
        dim3 g(cd(NHEADS * CC1, 128), cd(NN, 128));
        gemm_k<false, false><<<g, blk, GSMEM_BYTES, s0>>>(xin, w1, nullptr, xp1, NN, NHEADS * CC1, HH, nullptr);
    }
    asad_k<<<cd(NN * NHEADS, 256), 256, 0, s0>>>(xp1, a_src1, a_dst1, as1, ad1, NHEADS, CC1);
    edgeA_k<<<cd((long)ETOT * NHEADS, 256), 256, 0, s0>>>(as1, ad1, ei, e1, emax1, NHEADS);
    edgeB_k<<<cd((long)ETOT * NHEADS, 256), 256, 0, s0>>>(ei, e1, emax1, den1, NHEADS);
    edgeC_k<<<cd((long)ETOT * NHEADS * CC1 / 4, 256), 256, 0, s0>>>(xp1, e1, den1, ei, agg1, NHEADS, CC1);
    addbias_k<<<cd(NN * NHEADS * CC1, 256), 256, 0, s0>>>(agg1, b1, NHEADS * CC1, NN * NHEADS * CC1);

    // ---- GAT layer 2 (1 head x 100, mean == identity) ----
    {
        dim3 g(cd(CC2, 128), cd(NN, 128));
        gemm_k<false, false><<<g, blk, GSMEM_BYTES, s0>>>(agg1, w2, nullptr, xp2, NN, CC2, NHEADS * CC1, nullptr);
    }
    asad_k<<<cd(NN, 256), 256, 0, s0>>>(xp2, a_src2, a_dst2, as2, ad2, 1, CC2);
    edgeA_k<<<cd(ETOT, 256), 256, 0, s0>>>(as2, ad2, ei, e2, emax2, 1);
    edgeB_k<<<cd(ETOT, 256), 256, 0, s0>>>(ei, e2, emax2, den2, 1);
    edgeC_k<<<cd((long)ETOT * CC2 / 4, 256), 256, 0, s0>>>(xp2, e2, den2, ei, out, 1, CC2);
    addbias_k<<<cd(NN * CC2, 256), 256, 0, s0>>>(out, b2, CC2, NN * CC2);

    // ---- scalar losses ----
    scalars_k<<<1, 32, 0, s0>>>(acc, out, out_size);
}